// round 1
// baseline (speedup 1.0000x reference)
#include <cuda_runtime.h>
#include <math.h>

#define S_LEN  4096
#define NH     16
#define NKV    4
#define HD     64
#define QSIZE  1024      // NH*HD
#define KVSIZE 256       // NKV*HD
#define QKV_N  1536      // QSIZE + 2*KVSIZE
#define IN_DIM 2048      // 2*HID
#define HID    1024

// Scratch (device globals; no allocations allowed)
__device__ float g_qkv[S_LEN * QKV_N];    // 25.2 MB
__device__ float g_attn[S_LEN * QSIZE];   // 16.8 MB

// ---------------------------------------------------------------------------
// Generic NT SGEMM:  C[M,N] = A[M,K] @ B[N,K]^T   (both row-major, K fast dim)
// 128x128 block tile, BK=16, 256 threads, 8x8 per-thread microtile.
// Requires M%128==0, N%128==0, K%16==0 (true for all our shapes).
// ---------------------------------------------------------------------------
__global__ __launch_bounds__(256) void gemm_nt_kernel(
    const float* __restrict__ A, const float* __restrict__ B,
    float* __restrict__ C, int M, int N, int K)
{
    __shared__ float As[16][128];
    __shared__ float Bs[16][128];
    const int tid = threadIdx.x;
    const int tx = tid & 15;
    const int ty = tid >> 4;
    const int m0 = blockIdx.y * 128;
    const int n0 = blockIdx.x * 128;

    float acc[8][8];
#pragma unroll
    for (int i = 0; i < 8; i++)
#pragma unroll
        for (int j = 0; j < 8; j++) acc[i][j] = 0.f;

    for (int k0 = 0; k0 < K; k0 += 16) {
#pragma unroll
        for (int l = 0; l < 2; l++) {
            int idx = tid * 2 + l;          // 0..511
            int row = idx >> 2;             // 0..127
            int kq  = (idx & 3) * 4;        // 0,4,8,12
            float4 va = *(const float4*)(A + (size_t)(m0 + row) * K + k0 + kq);
            As[kq + 0][row] = va.x; As[kq + 1][row] = va.y;
            As[kq + 2][row] = va.z; As[kq + 3][row] = va.w;
            float4 vb = *(const float4*)(B + (size_t)(n0 + row) * K + k0 + kq);
            Bs[kq + 0][row] = vb.x; Bs[kq + 1][row] = vb.y;
            Bs[kq + 2][row] = vb.z; Bs[kq + 3][row] = vb.w;
        }
        __syncthreads();
#pragma unroll
        for (int kk = 0; kk < 16; kk++) {
            float a[8], b[8];
            *(float4*)&a[0] = *(const float4*)&As[kk][ty * 8];
            *(float4*)&a[4] = *(const float4*)&As[kk][ty * 8 + 4];
            *(float4*)&b[0] = *(const float4*)&Bs[kk][tx * 8];
            *(float4*)&b[4] = *(const float4*)&Bs[kk][tx * 8 + 4];
#pragma unroll
            for (int i = 0; i < 8; i++)
#pragma unroll
                for (int j = 0; j < 8; j++)
                    acc[i][j] = fmaf(a[i], b[j], acc[i][j]);
        }
        __syncthreads();
    }
#pragma unroll
    for (int i = 0; i < 8; i++) {
        float* crow = C + (size_t)(m0 + ty * 8 + i) * N + n0 + tx * 8;
        float4 v0 = {acc[i][0], acc[i][1], acc[i][2], acc[i][3]};
        float4 v1 = {acc[i][4], acc[i][5], acc[i][6], acc[i][7]};
        *(float4*)(crow)     = v0;
        *(float4*)(crow + 4) = v1;
    }
}

// ---------------------------------------------------------------------------
// RoPE applied in-place to q (heads 0..15) and k (4 heads at offset QSIZE).
// Phase math done in double: positions reach 4095 rad; fp32 phase rounding is
// the dominant error source vs the reference, keep ours at the fp64 level.
// ---------------------------------------------------------------------------
__global__ void rope_kernel(const int* __restrict__ positions)
{
    int idx = blockIdx.x * blockDim.x + threadIdx.x;
    const int total = S_LEN * (NH + NKV) * 32;
    if (idx >= total) return;
    int j = idx & 31;
    int h = (idx >> 5) % (NH + NKV);
    int s = idx / (32 * (NH + NKV));
    int off = (h < NH) ? h * HD : QSIZE + (h - NH) * HD;
    float* base = g_qkv + (size_t)s * QKV_N + off;

    double inv_freq = exp(-(double)j * (1.0 / 32.0) * log(10000.0));
    double f = (double)positions[s] * inv_freq;
    double cs, sn;
    sincos(f, &sn, &cs);
    float c = (float)cs, si = (float)sn;
    float x1 = base[j], x2 = base[j + 32];
    base[j]      = x1 * c - x2 * si;
    base[j + 32] = x2 * c + x1 * si;
}

// ---------------------------------------------------------------------------
// Causal GQA flash attention, fp32.
// Grid: (S/64 q-blocks, NH heads). Block: 256 threads (16x16), 4x4 microtile.
// Smem: Qs (Q^T, swizzled), KV (K^T swizzled, then V plain), Ps (probs,
// swizzled so PV column reads are conflict-free). Exactly 48 KB static.
// Online softmax state (m,l) replicated in registers via half-warp shfl.
// ---------------------------------------------------------------------------
#define XC(d, x)  ((x) ^ (((((d) >> 2)) & 15) << 2))   // for [d][x] transposed tiles
#define PSW(r, t) ((t) ^ (((r) & 7) << 2))             // for Ps[r][t]

__global__ __launch_bounds__(256) void flash_kernel()
{
    __shared__ float Qs[64][64];
    __shared__ float KV[64][64];
    __shared__ float Ps[64][64];

    const int tid = threadIdx.x;
    const int tx = tid & 15;
    const int ty = tid >> 4;
    const int qb = blockIdx.x;
    const int h  = blockIdx.y;
    const int kvh = h >> 2;                      // GQA: q head h -> kv head h/4
    const float* Qg = g_qkv + (size_t)h * HD;
    const float* Kg = g_qkv + QSIZE + (size_t)kvh * HD;
    const float* Vg = g_qkv + QSIZE + KVSIZE + (size_t)kvh * HD;
    const int r0 = ty * 4, c0 = tx * 4;

    // Load Q tile transposed + swizzled: Qs[d][row]
#pragma unroll
    for (int l = 0; l < 4; l++) {
        int idx = l * 256 + tid;                 // 0..1023
        int row = idx >> 4;                      // 0..63
        int d4  = (idx & 15) * 4;                // 0..60
        float4 v = *(const float4*)(Qg + (size_t)(qb * 64 + row) * QKV_N + d4);
        Qs[d4 + 0][XC(d4 + 0, row)] = v.x;
        Qs[d4 + 1][XC(d4 + 1, row)] = v.y;
        Qs[d4 + 2][XC(d4 + 2, row)] = v.z;
        Qs[d4 + 3][XC(d4 + 3, row)] = v.w;
    }

    float m_row[4], l_row[4], acc[4][4];
#pragma unroll
    for (int i = 0; i < 4; i++) {
        m_row[i] = -1e30f; l_row[i] = 0.f;
#pragma unroll
        for (int j = 0; j < 4; j++) acc[i][j] = 0.f;
    }

    for (int kb = 0; kb <= qb; kb++) {
        __syncthreads();   // prior PV done (iter0: Q load done) before KV overwrite
        // Load K tile transposed + swizzled: KV[d][col]
#pragma unroll
        for (int l = 0; l < 4; l++) {
            int idx = l * 256 + tid;
            int row = idx >> 4;
            int d4  = (idx & 15) * 4;
            float4 v = *(const float4*)(Kg + (size_t)(kb * 64 + row) * QKV_N + d4);
            KV[d4 + 0][XC(d4 + 0, row)] = v.x;
            KV[d4 + 1][XC(d4 + 1, row)] = v.y;
            KV[d4 + 2][XC(d4 + 2, row)] = v.z;
            KV[d4 + 3][XC(d4 + 3, row)] = v.w;
        }
        __syncthreads();

        // Scores: sf[i][j] = sum_d Q[r0+i][d] * K[c0+j][d]
        float sf[4][4];
#pragma unroll
        for (int i = 0; i < 4; i++)
#pragma unroll
            for (int j = 0; j < 4; j++) sf[i][j] = 0.f;
#pragma unroll 8
        for (int d = 0; d < 64; d++) {
            float4 a = *(const float4*)&Qs[d][XC(d, r0)];
            float4 b = *(const float4*)&KV[d][XC(d, c0)];
            float av[4] = {a.x, a.y, a.z, a.w};
            float bv[4] = {b.x, b.y, b.z, b.w};
#pragma unroll
            for (int i = 0; i < 4; i++)
#pragma unroll
                for (int j = 0; j < 4; j++)
                    sf[i][j] = fmaf(av[i], bv[j], sf[i][j]);
        }
        const bool diag = (kb == qb);
#pragma unroll
        for (int i = 0; i < 4; i++)
#pragma unroll
            for (int j = 0; j < 4; j++) {
                float s = sf[i][j] * 0.125f;     // HD^-0.5
                if (diag && (c0 + j > r0 + i)) s = -1e30f;
                sf[i][j] = s;
            }

        // Online softmax per row; reduce across the 16 tx lanes (half-warp)
#pragma unroll
        for (int i = 0; i < 4; i++) {
            float mx = fmaxf(fmaxf(sf[i][0], sf[i][1]), fmaxf(sf[i][2], sf[i][3]));
#pragma unroll
            for (int w = 8; w >= 1; w >>= 1)
                mx = fmaxf(mx, __shfl_xor_sync(0xffffffffu, mx, w));
            float nm = fmaxf(m_row[i], mx);
            float p0 = __expf(sf[i][0] - nm);
            float p1 = __expf(sf[i][1] - nm);
            float p2 = __expf(sf[i][2] - nm);
            float p3 = __expf(sf[i][3] - nm);
            float rs = (p0 + p1) + (p2 + p3);
#pragma unroll
            for (int w = 8; w >= 1; w >>= 1)
                rs += __shfl_xor_sync(0xffffffffu, rs, w);
            float alpha = __expf(m_row[i] - nm);
            l_row[i] = l_row[i] * alpha + rs;
            m_row[i] = nm;
            int r = r0 + i;
            float4 pv = {p0, p1, p2, p3};
            *(float4*)&Ps[r][PSW(r, c0)] = pv;
#pragma unroll
            for (int j = 0; j < 4; j++) acc[i][j] *= alpha;
        }
        __syncthreads();   // Ps fully written; KV (K) free

        // Load V tile plain: KV[t][d]
#pragma unroll
        for (int l = 0; l < 4; l++) {
            int idx = l * 256 + tid;
            int row = idx >> 4;
            int d4  = (idx & 15) * 4;
            float4 v = *(const float4*)(Vg + (size_t)(kb * 64 + row) * QKV_N + d4);
            *(float4*)&KV[row][d4] = v;
        }
        __syncthreads();

        // PV: acc[i][j] += sum_t P[r0+i][t] * V[t][c0+j]
#pragma unroll 8
        for (int t = 0; t < 64; t++) {
            float4 b = *(const float4*)&KV[t][c0];
            float a0 = Ps[r0 + 0][PSW(r0 + 0, t)];
            float a1 = Ps[r0 + 1][PSW(r0 + 1, t)];
            float a2 = Ps[r0 + 2][PSW(r0 + 2, t)];
            float a3 = Ps[r0 + 3][PSW(r0 + 3, t)];
            acc[0][0] = fmaf(a0, b.x, acc[0][0]);
            acc[0][1] = fmaf(a0, b.y, acc[0][1]);
            acc[0][2] = fmaf(a0, b.z, acc[0][2]);
            acc[0][3] = fmaf(a0, b.w, acc[0][3]);
            acc[1][0] = fmaf(a1, b.x, acc[1][0]);
            acc[1][1] = fmaf(a1, b.y, acc[1][1]);
            acc[1][2] = fmaf(a1, b.z, acc[1][2]);
            acc[1][3] = fmaf(a1, b.w, acc[1][3]);
            acc[2][0] = fmaf(a2, b.x, acc[2][0]);
            acc[2][1] = fmaf(a2, b.y, acc[2][1]);
            acc[2][2] = fmaf(a2, b.z, acc[2][2]);
            acc[2][3] = fmaf(a2, b.w, acc[2][3]);
            acc[3][0] = fmaf(a3, b.x, acc[3][0]);
            acc[3][1] = fmaf(a3, b.y, acc[3][1]);
            acc[3][2] = fmaf(a3, b.z, acc[3][2]);
            acc[3][3] = fmaf(a3, b.w, acc[3][3]);
        }
    }

    // Normalize and write attention output
#pragma unroll
    for (int i = 0; i < 4; i++) {
        float inv = 1.0f / l_row[i];
        float4 v = {acc[i][0] * inv, acc[i][1] * inv, acc[i][2] * inv, acc[i][3] * inv};
        *(float4*)(g_attn + (size_t)(qb * 64 + r0 + i) * QSIZE + h * HD + c0) = v;
    }
}

// ---------------------------------------------------------------------------
extern "C" void kernel_launch(void* const* d_in, const int* in_sizes, int n_in,
                              void* d_out, int out_size)
{
    const int*   positions = (const int*)d_in[0];
    const float* hidden    = (const float*)d_in[1];
    const float* w_qkv     = (const float*)d_in[2];
    const float* w_o       = (const float*)d_in[3];
    float*       out       = (float*)d_out;

    float* qkv = nullptr;
    float* attn = nullptr;
    cudaGetSymbolAddress((void**)&qkv, g_qkv);
    cudaGetSymbolAddress((void**)&attn, g_attn);

    // 1) qkv = hidden @ w_qkv^T   [4096,2048] x [1536,2048]^T
    gemm_nt_kernel<<<dim3(QKV_N / 128, S_LEN / 128), 256>>>(
        hidden, w_qkv, qkv, S_LEN, QKV_N, IN_DIM);

    // 2) RoPE in place on q,k
    const int rope_total = S_LEN * (NH + NKV) * 32;
    rope_kernel<<<(rope_total + 255) / 256, 256>>>(positions);

    // 3) causal GQA flash attention
    flash_kernel<<<dim3(S_LEN / 64, NH), 256>>>();

    // 4) out = attn @ w_o^T       [4096,1024] x [1024,1024]^T
    gemm_nt_kernel<<<dim3(HID / 128, S_LEN / 128), 256>>>(
        attn, w_o, out, S_LEN, HID, QSIZE);
}

// round 4
// speedup vs baseline: 1.3599x; 1.3599x over previous
#include <cuda_runtime.h>
#include <math.h>

#define S_LEN  4096
#define NH     16
#define NKV    4
#define HD     64
#define QSIZE  1024      // NH*HD
#define KVSIZE 256       // NKV*HD
#define QKV_N  1536      // QSIZE + 2*KVSIZE
#define IN_DIM 2048      // 2*HID
#define HID    1024

// Scratch (device globals; no allocations allowed)
__device__ float g_qkv[S_LEN * QKV_N];    // 25.2 MB
__device__ float g_attn[S_LEN * QSIZE];   // 16.8 MB

// ---------------------------------------------------------------------------
// Generic NT SGEMM (fp32):  C[M,N] = A[M,K] @ B[N,K]^T
// ---------------------------------------------------------------------------
__global__ __launch_bounds__(256) void gemm_nt_kernel(
    const float* __restrict__ A, const float* __restrict__ B,
    float* __restrict__ C, int M, int N, int K)
{
    __shared__ float As[16][128];
    __shared__ float Bs[16][128];
    const int tid = threadIdx.x;
    const int tx = tid & 15;
    const int ty = tid >> 4;
    const int m0 = blockIdx.y * 128;
    const int n0 = blockIdx.x * 128;

    float acc[8][8];
#pragma unroll
    for (int i = 0; i < 8; i++)
#pragma unroll
        for (int j = 0; j < 8; j++) acc[i][j] = 0.f;

    for (int k0 = 0; k0 < K; k0 += 16) {
#pragma unroll
        for (int l = 0; l < 2; l++) {
            int idx = tid * 2 + l;
            int row = idx >> 2;
            int kq  = (idx & 3) * 4;
            float4 va = *(const float4*)(A + (size_t)(m0 + row) * K + k0 + kq);
            As[kq + 0][row] = va.x; As[kq + 1][row] = va.y;
            As[kq + 2][row] = va.z; As[kq + 3][row] = va.w;
            float4 vb = *(const float4*)(B + (size_t)(n0 + row) * K + k0 + kq);
            Bs[kq + 0][row] = vb.x; Bs[kq + 1][row] = vb.y;
            Bs[kq + 2][row] = vb.z; Bs[kq + 3][row] = vb.w;
        }
        __syncthreads();
#pragma unroll
        for (int kk = 0; kk < 16; kk++) {
            float a[8], b[8];
            *(float4*)&a[0] = *(const float4*)&As[kk][ty * 8];
            *(float4*)&a[4] = *(const float4*)&As[kk][ty * 8 + 4];
            *(float4*)&b[0] = *(const float4*)&Bs[kk][tx * 8];
            *(float4*)&b[4] = *(const float4*)&Bs[kk][tx * 8 + 4];
#pragma unroll
            for (int i = 0; i < 8; i++)
#pragma unroll
                for (int j = 0; j < 8; j++)
                    acc[i][j] = fmaf(a[i], b[j], acc[i][j]);
        }
        __syncthreads();
    }
#pragma unroll
    for (int i = 0; i < 8; i++) {
        float* crow = C + (size_t)(m0 + ty * 8 + i) * N + n0 + tx * 8;
        float4 v0 = {acc[i][0], acc[i][1], acc[i][2], acc[i][3]};
        float4 v1 = {acc[i][4], acc[i][5], acc[i][6], acc[i][7]};
        *(float4*)(crow)     = v0;
        *(float4*)(crow + 4) = v1;
    }
}

// ---------------------------------------------------------------------------
// RoPE (phase in fp64 — positions reach 4095 rad)
// ---------------------------------------------------------------------------
__global__ void rope_kernel(const int* __restrict__ positions)
{
    int idx = blockIdx.x * blockDim.x + threadIdx.x;
    const int total = S_LEN * (NH + NKV) * 32;
    if (idx >= total) return;
    int j = idx & 31;
    int h = (idx >> 5) % (NH + NKV);
    int s = idx / (32 * (NH + NKV));
    int off = (h < NH) ? h * HD : QSIZE + (h - NH) * HD;
    float* base = g_qkv + (size_t)s * QKV_N + off;

    double inv_freq = exp(-(double)j * (1.0 / 32.0) * log(10000.0));
    double f = (double)positions[s] * inv_freq;
    double cs, sn;
    sincos(f, &sn, &cs);
    float c = (float)cs, si = (float)sn;
    float x1 = base[j], x2 = base[j + 32];
    base[j]      = x1 * c - x2 * si;
    base[j + 32] = x2 * c + x1 * si;
}

// ---------------------------------------------------------------------------
// tf32 helpers + mma.sync
// ---------------------------------------------------------------------------
__device__ __forceinline__ unsigned tf32_of(float x) {
    unsigned u;
    asm("cvt.rna.tf32.f32 %0, %1;" : "=r"(u) : "f"(x));
    return u;
}

__device__ __forceinline__ void mma_tf32(float* c, const unsigned* a, const unsigned* b) {
    asm volatile(
        "mma.sync.aligned.m16n8k8.row.col.f32.tf32.tf32.f32 "
        "{%0,%1,%2,%3}, {%4,%5,%6,%7}, {%8,%9}, {%0,%1,%2,%3};"
        : "+f"(c[0]), "+f"(c[1]), "+f"(c[2]), "+f"(c[3])
        : "r"(a[0]), "r"(a[1]), "r"(a[2]), "r"(a[3]), "r"(b[0]), "r"(b[1]));
}

// ---------------------------------------------------------------------------
// Causal GQA flash attention on tensor cores (tf32 mma.sync m16n8k8).
// Grid (S/64, NH), 128 threads = 4 warps; warp w owns Q rows [16w,16w+16).
// All smem tiles are stored FRAGMENT-MAJOR: each lane's operand regs for a
// given (tile,kstep) are contiguous (LDS.128 for A, LDS.64 for B) -> no bank
// conflicts, minimal LDS instruction count. P is converted C-frag -> A-frag
// purely via quad shuffles (no smem).
// ---------------------------------------------------------------------------
__global__ __launch_bounds__(128) void flash_tc_kernel()
{
    __shared__ unsigned Qf[4096];   // [wr(4)][k(8)][lane(32)][4] : A frags of Q
    __shared__ unsigned Kf[4096];   // [nt(8)][k(8)][lane(32)][2] : B frags of K^T
    __shared__ unsigned Vf[4096];   // [nt(8)][k(8)][lane(32)][2] : B frags of V

    const int tid  = threadIdx.x;
    const int lane = tid & 31;
    const int warp = tid >> 5;
    const int qb = blockIdx.x;
    const int h  = blockIdx.y;
    const int kvh = h >> 2;
    const float* Qg = g_qkv + (size_t)h * HD;
    const float* Kg = g_qkv + QSIZE + (size_t)kvh * HD;
    const float* Vg = g_qkv + QSIZE + KVSIZE + (size_t)kvh * HD;

    const int gq = lane >> 2;   // groupID: rows gq, gq+8 of warp tile
    const int tq = lane & 3;

    // ---- stage Q once (scale 1/8 folded in, tf32) in A-fragment layout ----
#pragma unroll
    for (int l = 0; l < 8; l++) {
        int idx = l * 128 + tid;
        int row = idx >> 4;            // 0..63
        int d4  = (idx & 15) * 4;
        float4 v = *(const float4*)(Qg + (size_t)(qb * 64 + row) * QKV_N + d4);
        float vv[4] = {v.x, v.y, v.z, v.w};
        int wr = row >> 4, r = row & 15;
#pragma unroll
        for (int e = 0; e < 4; e++) {
            int d = d4 + e;
            int k = d >> 3, dk = d & 7;
            int ln   = ((r & 7) << 2) | (dk & 3);
            int comp = (r >> 3) | ((dk >> 2) << 1);
            Qf[(((wr << 3) | k) << 7) + (ln << 2) + comp] = tf32_of(vv[e] * 0.125f);
        }
    }

    float m_s[2] = {-1e30f, -1e30f};
    float l_s[2] = {0.f, 0.f};
    float acc_o[8][4];
#pragma unroll
    for (int i = 0; i < 8; i++)
#pragma unroll
        for (int j = 0; j < 4; j++) acc_o[i][j] = 0.f;

    for (int kb = 0; kb <= qb; kb++) {
        __syncthreads();   // prior iteration's mma reads of Kf/Vf done (iter0: Q staged)
        // ---- stage K, V tiles in B-fragment layout (tf32) ----
#pragma unroll
        for (int l = 0; l < 8; l++) {
            int idx = l * 128 + tid;
            int row = idx >> 4;        // kv position t, 0..63
            int d4  = (idx & 15) * 4;
            float4 kv = *(const float4*)(Kg + (size_t)(kb * 64 + row) * QKV_N + d4);
            float4 vv = *(const float4*)(Vg + (size_t)(kb * 64 + row) * QKV_N + d4);
            float kk[4] = {kv.x, kv.y, kv.z, kv.w};
            float vl[4] = {vv.x, vv.y, vv.z, vv.w};
#pragma unroll
            for (int e = 0; e < 4; e++) {
                int d = d4 + e;
                // K: B frag of (nt = t>>3, k = d>>3); lane = ((t&7)<<2)|(d&3); comp = (d>>2)&1
                Kf[(((row >> 3) * 8 + (d >> 3)) << 6) +
                   ((((row & 7) << 2) | (d & 3)) << 1) + ((d >> 2) & 1)] = tf32_of(kk[e]);
                // V: B frag of (nt = d>>3, k = t>>3); lane = ((d&7)<<2)|(t&3); comp = (t>>2)&1
                Vf[(((d >> 3) * 8 + (row >> 3)) << 6) +
                   ((((d & 7) << 2) | (row & 3)) << 1) + ((row >> 2) & 1)] = tf32_of(vl[e]);
            }
        }
        __syncthreads();

        // ---- S = (Q*scale) @ K^T via 8 ksteps x 8 ntiles ----
        float s[8][4];
#pragma unroll
        for (int nt = 0; nt < 8; nt++)
#pragma unroll
            for (int j = 0; j < 4; j++) s[nt][j] = 0.f;
#pragma unroll
        for (int k = 0; k < 8; k++) {
            unsigned a[4];
            *(uint4*)a = *(const uint4*)&Qf[(((warp << 3) | k) << 7) + (lane << 2)];
#pragma unroll
            for (int nt = 0; nt < 8; nt++) {
                unsigned b[2];
                *(uint2*)b = *(const uint2*)&Kf[(((nt << 3) | k) << 6) + (lane << 1)];
                mma_tf32(s[nt], a, b);
            }
        }

        // ---- causal mask on diagonal tile ----
        const int qrow0 = (warp << 4) + gq;  // local row of c0,c1 (c2,c3 at +8)
        if (kb == qb) {
#pragma unroll
            for (int nt = 0; nt < 8; nt++) {
                int cb = (nt << 3) + (tq << 1);
                if (cb     > qrow0)     s[nt][0] = -1e30f;
                if (cb + 1 > qrow0)     s[nt][1] = -1e30f;
                if (cb     > qrow0 + 8) s[nt][2] = -1e30f;
                if (cb + 1 > qrow0 + 8) s[nt][3] = -1e30f;
            }
        }

        // ---- online softmax (rows gq, gq+8; state replicated per quad) ----
        float mx0 = -1e30f, mx1 = -1e30f;
#pragma unroll
        for (int nt = 0; nt < 8; nt++) {
            mx0 = fmaxf(mx0, fmaxf(s[nt][0], s[nt][1]));
            mx1 = fmaxf(mx1, fmaxf(s[nt][2], s[nt][3]));
        }
        mx0 = fmaxf(mx0, __shfl_xor_sync(0xffffffffu, mx0, 1));
        mx0 = fmaxf(mx0, __shfl_xor_sync(0xffffffffu, mx0, 2));
        mx1 = fmaxf(mx1, __shfl_xor_sync(0xffffffffu, mx1, 1));
        mx1 = fmaxf(mx1, __shfl_xor_sync(0xffffffffu, mx1, 2));
        float nm0 = fmaxf(m_s[0], mx0), nm1 = fmaxf(m_s[1], mx1);
        float al0 = __expf(m_s[0] - nm0), al1 = __expf(m_s[1] - nm1);
        m_s[0] = nm0; m_s[1] = nm1;

        float sum0 = 0.f, sum1 = 0.f;
#pragma unroll
        for (int nt = 0; nt < 8; nt++) {
            s[nt][0] = __expf(s[nt][0] - nm0);
            s[nt][1] = __expf(s[nt][1] - nm0);
            s[nt][2] = __expf(s[nt][2] - nm1);
            s[nt][3] = __expf(s[nt][3] - nm1);
            sum0 += s[nt][0] + s[nt][1];
            sum1 += s[nt][2] + s[nt][3];
        }
        sum0 += __shfl_xor_sync(0xffffffffu, sum0, 1);
        sum0 += __shfl_xor_sync(0xffffffffu, sum0, 2);
        sum1 += __shfl_xor_sync(0xffffffffu, sum1, 1);
        sum1 += __shfl_xor_sync(0xffffffffu, sum1, 2);
        l_s[0] = l_s[0] * al0 + sum0;
        l_s[1] = l_s[1] * al1 + sum1;

#pragma unroll
        for (int nt = 0; nt < 8; nt++) {
            acc_o[nt][0] *= al0; acc_o[nt][1] *= al0;
            acc_o[nt][2] *= al1; acc_o[nt][3] *= al1;
        }

        // ---- PV: for each kv kstep k, build P A-frag from C-frag via quad
        //      shuffles, then mma over 8 HD ntiles ----
        const int src_lo = (lane & ~3) | (tq >> 1);
        const int src_hi = src_lo | 2;
        const bool odd = (tq & 1);
#pragma unroll
        for (int k = 0; k < 8; k++) {
            float v0, v1;
            unsigned pa[4];
            v0 = __shfl_sync(0xffffffffu, s[k][0], src_lo);
            v1 = __shfl_sync(0xffffffffu, s[k][1], src_lo);
            pa[0] = tf32_of(odd ? v1 : v0);
            v0 = __shfl_sync(0xffffffffu, s[k][2], src_lo);
            v1 = __shfl_sync(0xffffffffu, s[k][3], src_lo);
            pa[1] = tf32_of(odd ? v1 : v0);
            v0 = __shfl_sync(0xffffffffu, s[k][0], src_hi);
            v1 = __shfl_sync(0xffffffffu, s[k][1], src_hi);
            pa[2] = tf32_of(odd ? v1 : v0);
            v0 = __shfl_sync(0xffffffffu, s[k][2], src_hi);
            v1 = __shfl_sync(0xffffffffu, s[k][3], src_hi);
            pa[3] = tf32_of(odd ? v1 : v0);
#pragma unroll
            for (int nt = 0; nt < 8; nt++) {
                unsigned b[2];
                *(uint2*)b = *(const uint2*)&Vf[(((nt << 3) | k) << 6) + (lane << 1)];
                mma_tf32(acc_o[nt], pa, b);
            }
        }
    }

    // ---- normalize + write ----
    float inv0 = 1.0f / l_s[0];
    float inv1 = 1.0f / l_s[1];
    int row0 = qb * 64 + (warp << 4) + gq;
#pragma unroll
    for (int nt = 0; nt < 8; nt++) {
        int col = h * HD + (nt << 3) + (tq << 1);
        float2 lo = {acc_o[nt][0] * inv0, acc_o[nt][1] * inv0};
        float2 hi = {acc_o[nt][2] * inv1, acc_o[nt][3] * inv1};
        *(float2*)(g_attn + (size_t)row0 * QSIZE + col)       = lo;
        *(float2*)(g_attn + (size_t)(row0 + 8) * QSIZE + col) = hi;
    }
}

// ---------------------------------------------------------------------------
extern "C" void kernel_launch(void* const* d_in, const int* in_sizes, int n_in,
                              void* d_out, int out_size)
{
    const int*   positions = (const int*)d_in[0];
    const float* hidden    = (const float*)d_in[1];
    const float* w_qkv     = (const float*)d_in[2];
    const float* w_o       = (const float*)d_in[3];
    float*       out       = (float*)d_out;

    float* qkv = nullptr;
    float* attn = nullptr;
    cudaGetSymbolAddress((void**)&qkv, g_qkv);
    cudaGetSymbolAddress((void**)&attn, g_attn);

    // 1) qkv = hidden @ w_qkv^T
    gemm_nt_kernel<<<dim3(QKV_N / 128, S_LEN / 128), 256>>>(
        hidden, w_qkv, qkv, S_LEN, QKV_N, IN_DIM);

    // 2) RoPE in place on q,k
    const int rope_total = S_LEN * (NH + NKV) * 32;
    rope_kernel<<<(rope_total + 255) / 256, 256>>>(positions);

    // 3) causal GQA flash attention (tf32 tensor cores)
    flash_tc_kernel<<<dim3(S_LEN / 64, NH), 128>>>();

    // 4) out = attn @ w_o^T
    gemm_nt_kernel<<<dim3(HID / 128, S_LEN / 128), 256>>>(
        attn, w_o, out, S_LEN, HID, QSIZE);
}

// round 5
// speedup vs baseline: 1.4386x; 1.0578x over previous
#include <cuda_runtime.h>
#include <math.h>

#define S_LEN  4096
#define NH     16
#define NKV    4
#define HD     64
#define QSIZE  1024      // NH*HD
#define KVSIZE 256       // NKV*HD
#define QKV_N  1536      // QSIZE + 2*KVSIZE
#define IN_DIM 2048      // 2*HID
#define HID    1024

// Scratch (device globals; no allocations allowed)
__device__ float g_qkv[S_LEN * QKV_N];        // 25.2 MB
__device__ float g_attn[S_LEN * QSIZE];       // 16.8 MB
// Fragment-major tensors for mma.sync (tf32 bit patterns)
__device__ unsigned g_qf[NH * 256 * 8 * 128]; // 16.8 MB : [h][mt(256)][k(8)][lane(32)][4]
__device__ unsigned g_kf[NKV * 512 * 8 * 64]; //  4.2 MB : [kvh][tb(512)][k(8)][lane(32)][2]
__device__ unsigned g_vf[NKV * 512 * 8 * 64]; //  4.2 MB : [kvh][t8(512)][ntd(8)][lane(32)][2]

// ---------------------------------------------------------------------------
// Generic NT SGEMM (fp32):  C[M,N] = A[M,K] @ B[N,K]^T
// ---------------------------------------------------------------------------
__global__ __launch_bounds__(256) void gemm_nt_kernel(
    const float* __restrict__ A, const float* __restrict__ B,
    float* __restrict__ C, int M, int N, int K)
{
    __shared__ float As[16][128];
    __shared__ float Bs[16][128];
    const int tid = threadIdx.x;
    const int tx = tid & 15;
    const int ty = tid >> 4;
    const int m0 = blockIdx.y * 128;
    const int n0 = blockIdx.x * 128;

    float acc[8][8];
#pragma unroll
    for (int i = 0; i < 8; i++)
#pragma unroll
        for (int j = 0; j < 8; j++) acc[i][j] = 0.f;

    for (int k0 = 0; k0 < K; k0 += 16) {
#pragma unroll
        for (int l = 0; l < 2; l++) {
            int idx = tid * 2 + l;
            int row = idx >> 2;
            int kq  = (idx & 3) * 4;
            float4 va = *(const float4*)(A + (size_t)(m0 + row) * K + k0 + kq);
            As[kq + 0][row] = va.x; As[kq + 1][row] = va.y;
            As[kq + 2][row] = va.z; As[kq + 3][row] = va.w;
            float4 vb = *(const float4*)(B + (size_t)(n0 + row) * K + k0 + kq);
            Bs[kq + 0][row] = vb.x; Bs[kq + 1][row] = vb.y;
            Bs[kq + 2][row] = vb.z; Bs[kq + 3][row] = vb.w;
        }
        __syncthreads();
#pragma unroll
        for (int kk = 0; kk < 16; kk++) {
            float a[8], b[8];
            *(float4*)&a[0] = *(const float4*)&As[kk][ty * 8];
            *(float4*)&a[4] = *(const float4*)&As[kk][ty * 8 + 4];
            *(float4*)&b[0] = *(const float4*)&Bs[kk][tx * 8];
            *(float4*)&b[4] = *(const float4*)&Bs[kk][tx * 8 + 4];
#pragma unroll
            for (int i = 0; i < 8; i++)
#pragma unroll
                for (int j = 0; j < 8; j++)
                    acc[i][j] = fmaf(a[i], b[j], acc[i][j]);
        }
        __syncthreads();
    }
#pragma unroll
    for (int i = 0; i < 8; i++) {
        float* crow = C + (size_t)(m0 + ty * 8 + i) * N + n0 + tx * 8;
        float4 v0 = {acc[i][0], acc[i][1], acc[i][2], acc[i][3]};
        float4 v1 = {acc[i][4], acc[i][5], acc[i][6], acc[i][7]};
        *(float4*)(crow)     = v0;
        *(float4*)(crow + 4) = v1;
    }
}

// ---------------------------------------------------------------------------
// RoPE (phase in fp64 — positions reach 4095 rad)
// ---------------------------------------------------------------------------
__global__ void rope_kernel(const int* __restrict__ positions)
{
    int idx = blockIdx.x * blockDim.x + threadIdx.x;
    const int total = S_LEN * (NH + NKV) * 32;
    if (idx >= total) return;
    int j = idx & 31;
    int h = (idx >> 5) % (NH + NKV);
    int s = idx / (32 * (NH + NKV));
    int off = (h < NH) ? h * HD : QSIZE + (h - NH) * HD;
    float* base = g_qkv + (size_t)s * QKV_N + off;

    double inv_freq = exp(-(double)j * (1.0 / 32.0) * log(10000.0));
    double f = (double)positions[s] * inv_freq;
    double cs, sn;
    sincos(f, &sn, &cs);
    float c = (float)cs, si = (float)sn;
    float x1 = base[j], x2 = base[j + 32];
    base[j]      = x1 * c - x2 * si;
    base[j + 32] = x2 * c + x1 * si;
}

// ---------------------------------------------------------------------------
// tf32 helpers + mma.sync
// ---------------------------------------------------------------------------
__device__ __forceinline__ unsigned tf32_of(float x) {
    unsigned u;
    asm("cvt.rna.tf32.f32 %0, %1;" : "=r"(u) : "f"(x));
    return u;
}

__device__ __forceinline__ void mma_tf32(float* c, const unsigned* a, const unsigned* b) {
    asm volatile(
        "mma.sync.aligned.m16n8k8.row.col.f32.tf32.tf32.f32 "
        "{%0,%1,%2,%3}, {%4,%5,%6,%7}, {%8,%9}, {%0,%1,%2,%3};"
        : "+f"(c[0]), "+f"(c[1]), "+f"(c[2]), "+f"(c[3])
        : "r"(a[0]), "r"(a[1]), "r"(a[2]), "r"(a[3]), "r"(b[0]), "r"(b[1]));
}

// ---------------------------------------------------------------------------
// One-time fragment conversion (after RoPE):
//   Q -> g_qf  (A-frag layout, scale 1/8 folded in)
//   K -> g_kf  (B-frag layout for S = Q @ K^T)
//   V -> g_vf  (B-frag layout for O = P @ V)
// Same index mappings as validated in the R4 staging code.
// ---------------------------------------------------------------------------
__global__ void convert_frag_kernel()
{
    int stride = gridDim.x * blockDim.x;
    // --- Q: S_LEN*QSIZE elements ---
    for (int idx = blockIdx.x * blockDim.x + threadIdx.x;
         idx < S_LEN * QSIZE; idx += stride) {
        int row = idx >> 10;
        int c   = idx & 1023;
        int h = c >> 6, d = c & 63;
        float v = g_qkv[(size_t)row * QKV_N + c] * 0.125f;
        int mt = row >> 4, r = row & 15;
        int k = d >> 3, dk = d & 7;
        int ln   = ((r & 7) << 2) | (dk & 3);
        int comp = (r >> 3) | ((dk >> 2) << 1);
        g_qf[(((h * 256 + mt) * 8 + k) << 7) + (ln << 2) + comp] = tf32_of(v);
    }
    // --- K: S_LEN*KVSIZE elements ---
    for (int idx = blockIdx.x * blockDim.x + threadIdx.x;
         idx < S_LEN * KVSIZE; idx += stride) {
        int row = idx >> 8;             // t
        int c   = idx & 255;
        int kvh = c >> 6, d = c & 63;
        float v = g_qkv[(size_t)row * QKV_N + QSIZE + c];
        g_kf[(((kvh * 512 + (row >> 3)) * 8 + (d >> 3)) << 6) +
             ((((row & 7) << 2) | (d & 3)) << 1) + ((d >> 2) & 1)] = tf32_of(v);
    }
    // --- V: S_LEN*KVSIZE elements ---
    for (int idx = blockIdx.x * blockDim.x + threadIdx.x;
         idx < S_LEN * KVSIZE; idx += stride) {
        int row = idx >> 8;             // t
        int c   = idx & 255;
        int kvh = c >> 6, d = c & 63;
        float v = g_qkv[(size_t)row * QKV_N + QSIZE + KVSIZE + c];
        g_vf[(((kvh * 512 + (row >> 3)) * 8 + (d >> 3)) << 6) +
             ((((d & 7) << 2) | (row & 3)) << 1) + ((row >> 2) & 1)] = tf32_of(v);
    }
}

// ---------------------------------------------------------------------------
// Causal GQA flash attention, tf32 mma.sync, ZERO shared memory / barriers.
// Grid (S/64, NH), 128 threads = 4 warps; warp w owns Q m-tile qb*4+w.
// Q A-frags live in registers; K/V B-frags loaded straight from the
// fragment-major global arrays (coalesced 256B/warp LDG.64, L1-cached,
// offsets are compile-time immediates off a per-iteration base).
// ---------------------------------------------------------------------------
__global__ __launch_bounds__(128) void flash_tc_kernel()
{
    const int lane = threadIdx.x & 31;
    const int warp = threadIdx.x >> 5;
    const int qb = blockIdx.x;
    const int h  = blockIdx.y;
    const int kvh = h >> 2;

    const int gq = lane >> 2;
    const int tq = lane & 3;

    // Q fragments for this warp's m16 tile (scale already folded)
    unsigned qa[8][4];
    {
        const uint4* qf = (const uint4*)(g_qf + (((size_t)(h * 256 + qb * 4 + warp) * 8) << 7));
#pragma unroll
        for (int k = 0; k < 8; k++)
            *(uint4*)qa[k] = qf[(k << 5) + lane];
    }

    float m_s[2] = {-1e30f, -1e30f};
    float l_s[2] = {0.f, 0.f};
    float acc_o[8][4];
#pragma unroll
    for (int i = 0; i < 8; i++)
#pragma unroll
        for (int j = 0; j < 4; j++) acc_o[i][j] = 0.f;

    const int src_lo = (lane & ~3) | (tq >> 1);
    const int src_hi = src_lo | 2;
    const bool odd = (tq & 1);
    const int qrow0 = (warp << 4) + gq;

    for (int kb = 0; kb <= qb; kb++) {
        const uint2* kf = (const uint2*)(g_kf + (((size_t)(kvh * 512 + kb * 8) * 8) << 6));
        const uint2* vf = (const uint2*)(g_vf + (((size_t)(kvh * 512 + kb * 8) * 8) << 6));

        // ---- S = (Q*scale) @ K^T : 8 ksteps x 8 ntiles ----
        float s[8][4];
#pragma unroll
        for (int nt = 0; nt < 8; nt++)
#pragma unroll
            for (int j = 0; j < 4; j++) s[nt][j] = 0.f;
#pragma unroll
        for (int k = 0; k < 8; k++) {
            unsigned b[8][2];
#pragma unroll
            for (int nt = 0; nt < 8; nt++)
                *(uint2*)b[nt] = kf[(((nt << 3) | k) << 5) + lane];
#pragma unroll
            for (int nt = 0; nt < 8; nt++)
                mma_tf32(s[nt], qa[k], b[nt]);
        }

        // ---- causal mask on diagonal tile ----
        if (kb == qb) {
#pragma unroll
            for (int nt = 0; nt < 8; nt++) {
                int cb = (nt << 3) + (tq << 1);
                if (cb     > qrow0)     s[nt][0] = -1e30f;
                if (cb + 1 > qrow0)     s[nt][1] = -1e30f;
                if (cb     > qrow0 + 8) s[nt][2] = -1e30f;
                if (cb + 1 > qrow0 + 8) s[nt][3] = -1e30f;
            }
        }

        // ---- online softmax (rows gq, gq+8; state replicated per quad) ----
        float mx0 = -1e30f, mx1 = -1e30f;
#pragma unroll
        for (int nt = 0; nt < 8; nt++) {
            mx0 = fmaxf(mx0, fmaxf(s[nt][0], s[nt][1]));
            mx1 = fmaxf(mx1, fmaxf(s[nt][2], s[nt][3]));
        }
        mx0 = fmaxf(mx0, __shfl_xor_sync(0xffffffffu, mx0, 1));
        mx0 = fmaxf(mx0, __shfl_xor_sync(0xffffffffu, mx0, 2));
        mx1 = fmaxf(mx1, __shfl_xor_sync(0xffffffffu, mx1, 1));
        mx1 = fmaxf(mx1, __shfl_xor_sync(0xffffffffu, mx1, 2));
        float nm0 = fmaxf(m_s[0], mx0), nm1 = fmaxf(m_s[1], mx1);
        float al0 = __expf(m_s[0] - nm0), al1 = __expf(m_s[1] - nm1);
        m_s[0] = nm0; m_s[1] = nm1;

        float sum0 = 0.f, sum1 = 0.f;
#pragma unroll
        for (int nt = 0; nt < 8; nt++) {
            s[nt][0] = __expf(s[nt][0] - nm0);
            s[nt][1] = __expf(s[nt][1] - nm0);
            s[nt][2] = __expf(s[nt][2] - nm1);
            s[nt][3] = __expf(s[nt][3] - nm1);
            sum0 += s[nt][0] + s[nt][1];
            sum1 += s[nt][2] + s[nt][3];
        }
        sum0 += __shfl_xor_sync(0xffffffffu, sum0, 1);
        sum0 += __shfl_xor_sync(0xffffffffu, sum0, 2);
        sum1 += __shfl_xor_sync(0xffffffffu, sum1, 1);
        sum1 += __shfl_xor_sync(0xffffffffu, sum1, 2);
        l_s[0] = l_s[0] * al0 + sum0;
        l_s[1] = l_s[1] * al1 + sum1;

#pragma unroll
        for (int nt = 0; nt < 8; nt++) {
            acc_o[nt][0] *= al0; acc_o[nt][1] *= al0;
            acc_o[nt][2] *= al1; acc_o[nt][3] *= al1;
        }

        // ---- PV: per kv kstep, P C-frag -> A-frag via quad shuffles ----
#pragma unroll
        for (int k = 0; k < 8; k++) {
            float v0, v1;
            unsigned pa[4];
            v0 = __shfl_sync(0xffffffffu, s[k][0], src_lo);
            v1 = __shfl_sync(0xffffffffu, s[k][1], src_lo);
            pa[0] = tf32_of(odd ? v1 : v0);
            v0 = __shfl_sync(0xffffffffu, s[k][2], src_lo);
            v1 = __shfl_sync(0xffffffffu, s[k][3], src_lo);
            pa[1] = tf32_of(odd ? v1 : v0);
            v0 = __shfl_sync(0xffffffffu, s[k][0], src_hi);
            v1 = __shfl_sync(0xffffffffu, s[k][1], src_hi);
            pa[2] = tf32_of(odd ? v1 : v0);
            v0 = __shfl_sync(0xffffffffu, s[k][2], src_hi);
            v1 = __shfl_sync(0xffffffffu, s[k][3], src_hi);
            pa[3] = tf32_of(odd ? v1 : v0);
            unsigned b[8][2];
#pragma unroll
            for (int nt = 0; nt < 8; nt++)
                *(uint2*)b[nt] = vf[(((k << 3) | nt) << 5) + lane];
#pragma unroll
            for (int nt = 0; nt < 8; nt++)
                mma_tf32(acc_o[nt], pa, b[nt]);
        }
    }

    // ---- normalize + write ----
    float inv0 = 1.0f / l_s[0];
    float inv1 = 1.0f / l_s[1];
    int row0 = qb * 64 + (warp << 4) + gq;
#pragma unroll
    for (int nt = 0; nt < 8; nt++) {
        int col = h * HD + (nt << 3) + (tq << 1);
        float2 lo = {acc_o[nt][0] * inv0, acc_o[nt][1] * inv0};
        float2 hi = {acc_o[nt][2] * inv1, acc_o[nt][3] * inv1};
        *(float2*)(g_attn + (size_t)row0 * QSIZE + col)       = lo;
        *(float2*)(g_attn + (size_t)(row0 + 8) * QSIZE + col) = hi;
    }
}

// ---------------------------------------------------------------------------
extern "C" void kernel_launch(void* const* d_in, const int* in_sizes, int n_in,
                              void* d_out, int out_size)
{
    const int*   positions = (const int*)d_in[0];
    const float* hidden    = (const float*)d_in[1];
    const float* w_qkv     = (const float*)d_in[2];
    const float* w_o       = (const float*)d_in[3];
    float*       out       = (float*)d_out;

    float* qkv = nullptr;
    float* attn = nullptr;
    cudaGetSymbolAddress((void**)&qkv, g_qkv);
    cudaGetSymbolAddress((void**)&attn, g_attn);

    // 1) qkv = hidden @ w_qkv^T
    gemm_nt_kernel<<<dim3(QKV_N / 128, S_LEN / 128), 256>>>(
        hidden, w_qkv, qkv, S_LEN, QKV_N, IN_DIM);

    // 2) RoPE in place on q,k
    const int rope_total = S_LEN * (NH + NKV) * 32;
    rope_kernel<<<(rope_total + 255) / 256, 256>>>(positions);

    // 3) one-time fragment conversion (Q,K,V -> mma layouts)
    convert_frag_kernel<<<1024, 256>>>();

    // 4) causal GQA flash attention (tf32 tensor cores, no smem)
    flash_tc_kernel<<<dim3(S_LEN / 64, NH), 128>>>();

    // 5) out = attn @ w_o^T
    gemm_nt_kernel<<<dim3(HID / 128, S_LEN / 128), 256>>>(
        attn, w_o, out, S_LEN, HID, QSIZE);
}

// round 6
// speedup vs baseline: 2.1397x; 1.4873x over previous
#include <cuda_runtime.h>
#include <math.h>

#define S_LEN  4096
#define NH     16
#define NKV    4
#define HD     64
#define QSIZE  1024      // NH*HD
#define KVSIZE 256       // NKV*HD
#define QKV_N  1536      // QSIZE + 2*KVSIZE
#define IN_DIM 2048      // 2*HID
#define HID    1024

// Scratch (device globals; no allocations allowed)
__device__ float g_qkv[S_LEN * QKV_N];        // 25.2 MB
__device__ float g_attn[S_LEN * QSIZE];       // 16.8 MB
// Fragment-major tensors for mma.sync (tf32 bit patterns)
__device__ unsigned g_qf[NH * 256 * 8 * 128]; // 16.8 MB : [h][mt(256)][k(8)][lane(32)][4]
__device__ unsigned g_kf[NKV * 512 * 8 * 64]; //  4.2 MB : [kvh][tb(512)][k(8)][lane(32)][2]
__device__ unsigned g_vf[NKV * 512 * 8 * 64]; //  4.2 MB : [kvh][t8(512)][ntd(8)][lane(32)][2]

// ---------------------------------------------------------------------------
// Generic NT SGEMM (fp32):  C[M,N] = A[M,K] @ B[N,K]^T
// ---------------------------------------------------------------------------
__global__ __launch_bounds__(256) void gemm_nt_kernel(
    const float* __restrict__ A, const float* __restrict__ B,
    float* __restrict__ C, int M, int N, int K)
{
    __shared__ float As[16][128];
    __shared__ float Bs[16][128];
    const int tid = threadIdx.x;
    const int tx = tid & 15;
    const int ty = tid >> 4;
    const int m0 = blockIdx.y * 128;
    const int n0 = blockIdx.x * 128;

    float acc[8][8];
#pragma unroll
    for (int i = 0; i < 8; i++)
#pragma unroll
        for (int j = 0; j < 8; j++) acc[i][j] = 0.f;

    for (int k0 = 0; k0 < K; k0 += 16) {
#pragma unroll
        for (int l = 0; l < 2; l++) {
            int idx = tid * 2 + l;
            int row = idx >> 2;
            int kq  = (idx & 3) * 4;
            float4 va = *(const float4*)(A + (size_t)(m0 + row) * K + k0 + kq);
            As[kq + 0][row] = va.x; As[kq + 1][row] = va.y;
            As[kq + 2][row] = va.z; As[kq + 3][row] = va.w;
            float4 vb = *(const float4*)(B + (size_t)(n0 + row) * K + k0 + kq);
            Bs[kq + 0][row] = vb.x; Bs[kq + 1][row] = vb.y;
            Bs[kq + 2][row] = vb.z; Bs[kq + 3][row] = vb.w;
        }
        __syncthreads();
#pragma unroll
        for (int kk = 0; kk < 16; kk++) {
            float a[8], b[8];
            *(float4*)&a[0] = *(const float4*)&As[kk][ty * 8];
            *(float4*)&a[4] = *(const float4*)&As[kk][ty * 8 + 4];
            *(float4*)&b[0] = *(const float4*)&Bs[kk][tx * 8];
            *(float4*)&b[4] = *(const float4*)&Bs[kk][tx * 8 + 4];
#pragma unroll
            for (int i = 0; i < 8; i++)
#pragma unroll
                for (int j = 0; j < 8; j++)
                    acc[i][j] = fmaf(a[i], b[j], acc[i][j]);
        }
        __syncthreads();
    }
#pragma unroll
    for (int i = 0; i < 8; i++) {
        float* crow = C + (size_t)(m0 + ty * 8 + i) * N + n0 + tx * 8;
        float4 v0 = {acc[i][0], acc[i][1], acc[i][2], acc[i][3]};
        float4 v1 = {acc[i][4], acc[i][5], acc[i][6], acc[i][7]};
        *(float4*)(crow)     = v0;
        *(float4*)(crow + 4) = v1;
    }
}

// ---------------------------------------------------------------------------
// RoPE. Reference computes phase in fp32 (positions_f32 * invfreq_f32), so we
// match that exactly: inv_freq table in fp64 once per block (32 lanes),
// rounded to fp32; phase in fp32; accurate sincosf (Payne-Hanek for big args).
// ---------------------------------------------------------------------------
__global__ void rope_kernel(const int* __restrict__ positions)
{
    __shared__ float invf_s[32];
    int tid = threadIdx.x;
    if (tid < 32)
        invf_s[tid] = (float)exp(-(double)tid * (1.0 / 32.0) * log(10000.0));
    __syncthreads();

    int idx = blockIdx.x * blockDim.x + tid;
    const int total = S_LEN * (NH + NKV) * 32;
    if (idx >= total) return;
    int j = idx & 31;
    int h = (idx >> 5) % (NH + NKV);
    int s = idx / (32 * (NH + NKV));
    int off = (h < NH) ? h * HD : QSIZE + (h - NH) * HD;
    float* base = g_qkv + (size_t)s * QKV_N + off;

    float f = (float)positions[s] * invf_s[j];
    float sn, c;
    sincosf(f, &sn, &c);
    float x1 = base[j], x2 = base[j + 32];
    base[j]      = x1 * c - x2 * sn;
    base[j + 32] = x2 * c + x1 * sn;
}

// ---------------------------------------------------------------------------
// tf32 helpers + mma.sync
// ---------------------------------------------------------------------------
__device__ __forceinline__ unsigned tf32_of(float x) {
    unsigned u;
    asm("cvt.rna.tf32.f32 %0, %1;" : "=r"(u) : "f"(x));
    return u;
}

__device__ __forceinline__ void mma_tf32(float* c, const unsigned* a, const unsigned* b) {
    asm volatile(
        "mma.sync.aligned.m16n8k8.row.col.f32.tf32.tf32.f32 "
        "{%0,%1,%2,%3}, {%4,%5,%6,%7}, {%8,%9}, {%0,%1,%2,%3};"
        : "+f"(c[0]), "+f"(c[1]), "+f"(c[2]), "+f"(c[3])
        : "r"(a[0]), "r"(a[1]), "r"(a[2]), "r"(a[3]), "r"(b[0]), "r"(b[1]));
}

// ---------------------------------------------------------------------------
// One-time fragment conversion (after RoPE): Q/K/V -> mma fragment layouts.
// ---------------------------------------------------------------------------
__global__ void convert_frag_kernel()
{
    int stride = gridDim.x * blockDim.x;
    for (int idx = blockIdx.x * blockDim.x + threadIdx.x;
         idx < S_LEN * QSIZE; idx += stride) {
        int row = idx >> 10;
        int c   = idx & 1023;
        int h = c >> 6, d = c & 63;
        float v = g_qkv[(size_t)row * QKV_N + c] * 0.125f;
        int mt = row >> 4, r = row & 15;
        int k = d >> 3, dk = d & 7;
        int ln   = ((r & 7) << 2) | (dk & 3);
        int comp = (r >> 3) | ((dk >> 2) << 1);
        g_qf[(((h * 256 + mt) * 8 + k) << 7) + (ln << 2) + comp] = tf32_of(v);
    }
    for (int idx = blockIdx.x * blockDim.x + threadIdx.x;
         idx < S_LEN * KVSIZE; idx += stride) {
        int row = idx >> 8;
        int c   = idx & 255;
        int kvh = c >> 6, d = c & 63;
        float v = g_qkv[(size_t)row * QKV_N + QSIZE + c];
        g_kf[(((kvh * 512 + (row >> 3)) * 8 + (d >> 3)) << 6) +
             ((((row & 7) << 2) | (d & 3)) << 1) + ((d >> 2) & 1)] = tf32_of(v);
    }
    for (int idx = blockIdx.x * blockDim.x + threadIdx.x;
         idx < S_LEN * KVSIZE; idx += stride) {
        int row = idx >> 8;
        int c   = idx & 255;
        int kvh = c >> 6, d = c & 63;
        float v = g_qkv[(size_t)row * QKV_N + QSIZE + KVSIZE + c];
        g_vf[(((kvh * 512 + (row >> 3)) * 8 + (d >> 3)) << 6) +
             ((((d & 7) << 2) | (row & 3)) << 1) + ((row >> 2) & 1)] = tf32_of(v);
    }
}

// ---------------------------------------------------------------------------
// Causal GQA flash attention, tf32 mma.sync, no smem/barriers.
// LPT scheduling: qb = 63 - blockIdx.x (longest jobs launch first).
// Register ping-pong prefetch: K k+1 during S-MMAs of k; V k=0 issued before
// softmax; next kb's K k=0 issued during last PV step.
// ---------------------------------------------------------------------------
__global__ __launch_bounds__(128, 3) void flash_tc_kernel()
{
    const int lane = threadIdx.x & 31;
    const int warp = threadIdx.x >> 5;
    const int qb = (int)gridDim.x - 1 - (int)blockIdx.x;   // LPT: big tiles first
    const int h  = blockIdx.y;
    const int kvh = h >> 2;

    const int gq = lane >> 2;
    const int tq = lane & 3;

    // Q fragments for this warp's m16 tile (scale already folded)
    unsigned qa[8][4];
    {
        const uint4* qf = (const uint4*)(g_qf + (((size_t)(h * 256 + qb * 4 + warp) * 8) << 7));
#pragma unroll
        for (int k = 0; k < 8; k++)
            *(uint4*)qa[k] = qf[(k << 5) + lane];
    }

    float m_s[2] = {-1e30f, -1e30f};
    float l_s[2] = {0.f, 0.f};
    float acc_o[8][4];
#pragma unroll
    for (int i = 0; i < 8; i++)
#pragma unroll
        for (int j = 0; j < 4; j++) acc_o[i][j] = 0.f;

    const int src_lo = (lane & ~3) | (tq >> 1);
    const int src_hi = src_lo | 2;
    const bool odd = (tq & 1);
    const int qrow0 = (warp << 4) + gq;

    const uint2* kf0 = (const uint2*)(g_kf + (((size_t)(kvh * 512) * 8) << 6));
    const uint2* vf0 = (const uint2*)(g_vf + (((size_t)(kvh * 512) * 8) << 6));

    uint2 buf[2][8];
    // prefetch K(kb=0, k=0)
#pragma unroll
    for (int nt = 0; nt < 8; nt++)
        buf[0][nt] = kf0[((nt << 3) << 5) + lane];

    for (int kb = 0; kb <= qb; kb++) {
        const uint2* kf = kf0 + (((size_t)(kb * 8) * 8) << 5);
        const uint2* vf = vf0 + (((size_t)(kb * 8) * 8) << 5);

        // ---- S = (Q*scale) @ K^T, prefetching K k+1 / V k=0 ----
        float s[8][4];
#pragma unroll
        for (int nt = 0; nt < 8; nt++)
#pragma unroll
            for (int j = 0; j < 4; j++) s[nt][j] = 0.f;
#pragma unroll
        for (int k = 0; k < 8; k++) {
            const int cur = k & 1, nxt = cur ^ 1;
            if (k < 7) {
#pragma unroll
                for (int nt = 0; nt < 8; nt++)
                    buf[nxt][nt] = kf[(((nt << 3) | (k + 1)) << 5) + lane];
            } else {
                // prefetch V(k=0) into the buffer freed at k=6
#pragma unroll
                for (int nt = 0; nt < 8; nt++)
                    buf[nxt][nt] = vf[(nt << 5) + lane];   // ((0<<3)|nt)
            }
#pragma unroll
            for (int nt = 0; nt < 8; nt++)
                mma_tf32(s[nt], qa[k], (const unsigned*)&buf[cur][nt]);
        }

        // ---- causal mask on diagonal tile ----
        if (kb == qb) {
#pragma unroll
            for (int nt = 0; nt < 8; nt++) {
                int cb = (nt << 3) + (tq << 1);
                if (cb     > qrow0)     s[nt][0] = -1e30f;
                if (cb + 1 > qrow0)     s[nt][1] = -1e30f;
                if (cb     > qrow0 + 8) s[nt][2] = -1e30f;
                if (cb + 1 > qrow0 + 8) s[nt][3] = -1e30f;
            }
        }

        // ---- online softmax (V k=0 loads in flight underneath) ----
        float mx0 = -1e30f, mx1 = -1e30f;
#pragma unroll
        for (int nt = 0; nt < 8; nt++) {
            mx0 = fmaxf(mx0, fmaxf(s[nt][0], s[nt][1]));
            mx1 = fmaxf(mx1, fmaxf(s[nt][2], s[nt][3]));
        }
        mx0 = fmaxf(mx0, __shfl_xor_sync(0xffffffffu, mx0, 1));
        mx0 = fmaxf(mx0, __shfl_xor_sync(0xffffffffu, mx0, 2));
        mx1 = fmaxf(mx1, __shfl_xor_sync(0xffffffffu, mx1, 1));
        mx1 = fmaxf(mx1, __shfl_xor_sync(0xffffffffu, mx1, 2));
        float nm0 = fmaxf(m_s[0], mx0), nm1 = fmaxf(m_s[1], mx1);
        float al0 = __expf(m_s[0] - nm0), al1 = __expf(m_s[1] - nm1);
        m_s[0] = nm0; m_s[1] = nm1;

        float sum0 = 0.f, sum1 = 0.f;
#pragma unroll
        for (int nt = 0; nt < 8; nt++) {
            s[nt][0] = __expf(s[nt][0] - nm0);
            s[nt][1] = __expf(s[nt][1] - nm0);
            s[nt][2] = __expf(s[nt][2] - nm1);
            s[nt][3] = __expf(s[nt][3] - nm1);
            sum0 += s[nt][0] + s[nt][1];
            sum1 += s[nt][2] + s[nt][3];
        }
        sum0 += __shfl_xor_sync(0xffffffffu, sum0, 1);
        sum0 += __shfl_xor_sync(0xffffffffu, sum0, 2);
        sum1 += __shfl_xor_sync(0xffffffffu, sum1, 1);
        sum1 += __shfl_xor_sync(0xffffffffu, sum1, 2);
        l_s[0] = l_s[0] * al0 + sum0;
        l_s[1] = l_s[1] * al1 + sum1;

#pragma unroll
        for (int nt = 0; nt < 8; nt++) {
            acc_o[nt][0] *= al0; acc_o[nt][1] *= al0;
            acc_o[nt][2] *= al1; acc_o[nt][3] *= al1;
        }

        // ---- PV, prefetching V k+1 / next kb's K k=0 ----
        const bool more = (kb < qb);
        const uint2* kf_next = kf + ((8 * 8) << 5);
#pragma unroll
        for (int k = 0; k < 8; k++) {
            const int cur = k & 1, nxt = cur ^ 1;
            if (k < 7) {
#pragma unroll
                for (int nt = 0; nt < 8; nt++)
                    buf[nxt][nt] = vf[((((k + 1) << 3) | nt) << 5) + lane];
            } else if (more) {
#pragma unroll
                for (int nt = 0; nt < 8; nt++)
                    buf[nxt][nt] = kf_next[((nt << 3) << 5) + lane];
            }
            float v0, v1;
            unsigned pa[4];
            v0 = __shfl_sync(0xffffffffu, s[k][0], src_lo);
            v1 = __shfl_sync(0xffffffffu, s[k][1], src_lo);
            pa[0] = tf32_of(odd ? v1 : v0);
            v0 = __shfl_sync(0xffffffffu, s[k][2], src_lo);
            v1 = __shfl_sync(0xffffffffu, s[k][3], src_lo);
            pa[1] = tf32_of(odd ? v1 : v0);
            v0 = __shfl_sync(0xffffffffu, s[k][0], src_hi);
            v1 = __shfl_sync(0xffffffffu, s[k][1], src_hi);
            pa[2] = tf32_of(odd ? v1 : v0);
            v0 = __shfl_sync(0xffffffffu, s[k][2], src_hi);
            v1 = __shfl_sync(0xffffffffu, s[k][3], src_hi);
            pa[3] = tf32_of(odd ? v1 : v0);
#pragma unroll
            for (int nt = 0; nt < 8; nt++)
                mma_tf32(acc_o[nt], pa, (const unsigned*)&buf[cur][nt]);
        }
    }

    // ---- normalize + write ----
    float inv0 = 1.0f / l_s[0];
    float inv1 = 1.0f / l_s[1];
    int row0 = qb * 64 + (warp << 4) + gq;
#pragma unroll
    for (int nt = 0; nt < 8; nt++) {
        int col = h * HD + (nt << 3) + (tq << 1);
        float2 lo = {acc_o[nt][0] * inv0, acc_o[nt][1] * inv0};
        float2 hi = {acc_o[nt][2] * inv1, acc_o[nt][3] * inv1};
        *(float2*)(g_attn + (size_t)row0 * QSIZE + col)       = lo;
        *(float2*)(g_attn + (size_t)(row0 + 8) * QSIZE + col) = hi;
    }
}

// ---------------------------------------------------------------------------
extern "C" void kernel_launch(void* const* d_in, const int* in_sizes, int n_in,
                              void* d_out, int out_size)
{
    const int*   positions = (const int*)d_in[0];
    const float* hidden    = (const float*)d_in[1];
    const float* w_qkv     = (const float*)d_in[2];
    const float* w_o       = (const float*)d_in[3];
    float*       out       = (float*)d_out;

    float* qkv = nullptr;
    float* attn = nullptr;
    cudaGetSymbolAddress((void**)&qkv, g_qkv);
    cudaGetSymbolAddress((void**)&attn, g_attn);

    // 1) qkv = hidden @ w_qkv^T
    gemm_nt_kernel<<<dim3(QKV_N / 128, S_LEN / 128), 256>>>(
        hidden, w_qkv, qkv, S_LEN, QKV_N, IN_DIM);

    // 2) RoPE in place on q,k
    const int rope_total = S_LEN * (NH + NKV) * 32;
    rope_kernel<<<(rope_total + 255) / 256, 256>>>(positions);

    // 3) one-time fragment conversion (Q,K,V -> mma layouts)
    convert_frag_kernel<<<1024, 256>>>();

    // 4) causal GQA flash attention (tf32 tensor cores, no smem)
    flash_tc_kernel<<<dim3(S_LEN / 64, NH), 128>>>();

    // 5) out = attn @ w_o^T
    gemm_nt_kernel<<<dim3(HID / 128, S_LEN / 128), 256>>>(
        attn, w_o, out, S_LEN, HID, QSIZE);
}

// round 7
// speedup vs baseline: 2.3353x; 1.0914x over previous
#include <cuda_runtime.h>
#include <cuda_fp16.h>
#include <math.h>

#define S_LEN  4096
#define NH     16
#define NKV    4
#define HD     64
#define QSIZE  1024      // NH*HD
#define KVSIZE 256       // NKV*HD
#define QKV_N  1536      // QSIZE + 2*KVSIZE
#define IN_DIM 2048      // 2*HID
#define HID    1024

// Scratch (device globals; no allocations allowed)
__device__ float g_qkv[S_LEN * QKV_N];        // 25.2 MB
__device__ float g_attn[S_LEN * QSIZE];       // 16.8 MB
// fp16 fragment-major tensors for mma.sync m16n8k16
__device__ unsigned g_qf16[16 * 256 * 4 * 32 * 4]; // 8.4 MB : [h][mt][kk][lane][4]
__device__ unsigned g_kf16[4 * 512 * 4 * 32 * 2];  // 2.1 MB : [kvh][tb][kk][lane][2]
__device__ unsigned g_vf16[4 * 256 * 8 * 32 * 2];  // 2.1 MB : [kvh][t16][nt][lane][2]

// ---------------------------------------------------------------------------
// Generic NT SGEMM (fp32):  C[M,N] = A[M,K] @ B[N,K]^T
// ---------------------------------------------------------------------------
__global__ __launch_bounds__(256) void gemm_nt_kernel(
    const float* __restrict__ A, const float* __restrict__ B,
    float* __restrict__ C, int M, int N, int K)
{
    __shared__ float As[16][128];
    __shared__ float Bs[16][128];
    const int tid = threadIdx.x;
    const int tx = tid & 15;
    const int ty = tid >> 4;
    const int m0 = blockIdx.y * 128;
    const int n0 = blockIdx.x * 128;

    float acc[8][8];
#pragma unroll
    for (int i = 0; i < 8; i++)
#pragma unroll
        for (int j = 0; j < 8; j++) acc[i][j] = 0.f;

    for (int k0 = 0; k0 < K; k0 += 16) {
#pragma unroll
        for (int l = 0; l < 2; l++) {
            int idx = tid * 2 + l;
            int row = idx >> 2;
            int kq  = (idx & 3) * 4;
            float4 va = *(const float4*)(A + (size_t)(m0 + row) * K + k0 + kq);
            As[kq + 0][row] = va.x; As[kq + 1][row] = va.y;
            As[kq + 2][row] = va.z; As[kq + 3][row] = va.w;
            float4 vb = *(const float4*)(B + (size_t)(n0 + row) * K + k0 + kq);
            Bs[kq + 0][row] = vb.x; Bs[kq + 1][row] = vb.y;
            Bs[kq + 2][row] = vb.z; Bs[kq + 3][row] = vb.w;
        }
        __syncthreads();
#pragma unroll
        for (int kk = 0; kk < 16; kk++) {
            float a[8], b[8];
            *(float4*)&a[0] = *(const float4*)&As[kk][ty * 8];
            *(float4*)&a[4] = *(const float4*)&As[kk][ty * 8 + 4];
            *(float4*)&b[0] = *(const float4*)&Bs[kk][tx * 8];
            *(float4*)&b[4] = *(const float4*)&Bs[kk][tx * 8 + 4];
#pragma unroll
            for (int i = 0; i < 8; i++)
#pragma unroll
                for (int j = 0; j < 8; j++)
                    acc[i][j] = fmaf(a[i], b[j], acc[i][j]);
        }
        __syncthreads();
    }
#pragma unroll
    for (int i = 0; i < 8; i++) {
        float* crow = C + (size_t)(m0 + ty * 8 + i) * N + n0 + tx * 8;
        float4 v0 = {acc[i][0], acc[i][1], acc[i][2], acc[i][3]};
        float4 v1 = {acc[i][4], acc[i][5], acc[i][6], acc[i][7]};
        *(float4*)(crow)     = v0;
        *(float4*)(crow + 4) = v1;
    }
}

// ---------------------------------------------------------------------------
// RoPE (phase fp32, matching the reference; inv_freq table in fp64 per block)
// ---------------------------------------------------------------------------
__global__ void rope_kernel(const int* __restrict__ positions)
{
    __shared__ float invf_s[32];
    int tid = threadIdx.x;
    if (tid < 32)
        invf_s[tid] = (float)exp(-(double)tid * (1.0 / 32.0) * log(10000.0));
    __syncthreads();

    int idx = blockIdx.x * blockDim.x + tid;
    const int total = S_LEN * (NH + NKV) * 32;
    if (idx >= total) return;
    int j = idx & 31;
    int h = (idx >> 5) % (NH + NKV);
    int s = idx / (32 * (NH + NKV));
    int off = (h < NH) ? h * HD : QSIZE + (h - NH) * HD;
    float* base = g_qkv + (size_t)s * QKV_N + off;

    float f = (float)positions[s] * invf_s[j];
    float sn, c;
    sincosf(f, &sn, &c);
    float x1 = base[j], x2 = base[j + 32];
    base[j]      = x1 * c - x2 * sn;
    base[j + 32] = x2 * c + x1 * sn;
}

// ---------------------------------------------------------------------------
// fp16 mma helpers
// ---------------------------------------------------------------------------
__device__ __forceinline__ void mma_f16(float* c, const unsigned* a, const unsigned* b) {
    asm volatile(
        "mma.sync.aligned.m16n8k16.row.col.f32.f16.f16.f32 "
        "{%0,%1,%2,%3}, {%4,%5,%6,%7}, {%8,%9}, {%0,%1,%2,%3};"
        : "+f"(c[0]), "+f"(c[1]), "+f"(c[2]), "+f"(c[3])
        : "r"(a[0]), "r"(a[1]), "r"(a[2]), "r"(a[3]), "r"(b[0]), "r"(b[1]));
}

__device__ __forceinline__ unsigned pack_h2(float lo, float hi) {
    __half2 h = __floats2half2_rn(lo, hi);
    return *(unsigned*)&h;
}

// ---------------------------------------------------------------------------
// One-time fragment conversion (after RoPE), vectorized float4 per iteration.
//
// m16n8k16 fragment maps (g = lane>>2, t = lane&3):
//  A (Q/P): a0=(g,2t|2t+1)  a1=(g+8,·)  a2=(g,2t+8|9)  a3=(g+8,·+8)
//  B (K):   b0={B[2t][g],B[2t+1][g]}  b1=rows+8 ; B[k=d][n=kv] = K[kv][d]
//  B (V):   same, B[k=t][n=d] = V[t][d]
// ---------------------------------------------------------------------------
__global__ void convert_frag_kernel()
{
    int stride = gridDim.x * blockDim.x;
    int tid0 = blockIdx.x * blockDim.x + threadIdx.x;

    // --- Q: float4 over d. 1,048,576 iters ---
    for (int i = tid0; i < S_LEN * QSIZE / 4; i += stride) {
        int row = i >> 8;                 // 256 float4 per row
        int c4  = (i & 255) * 4;          // 0..1020
        int h = c4 >> 6, d4 = c4 & 63;
        float4 v = *(const float4*)&g_qkv[(size_t)row * QKV_N + c4];
        int mt = row >> 4, r = row & 15, g = r & 7, hi = r >> 3;
        int kk = d4 >> 4;
        int word = hi | (((d4 >> 3) & 1) << 1);
        int t0 = (d4 & 7) >> 1;           // e=0,1 -> t0 ; e=2,3 -> t0+1
        unsigned* dst = g_qf16 +
            ((((size_t)(h * 256 + mt) * 4 + kk) * 32 + g * 4 + t0) << 2) + word;
        dst[0] = pack_h2(v.x * 0.125f, v.y * 0.125f);
        dst[4] = pack_h2(v.z * 0.125f, v.w * 0.125f);
    }

    // --- K: float4 over d. 262,144 iters ---
    for (int i = tid0; i < S_LEN * KVSIZE / 4; i += stride) {
        int row = i >> 6;                 // kv position t
        int c4  = (i & 63) * 4;
        int kvh = c4 >> 6, d4 = c4 & 63;
        float4 v = *(const float4*)&g_qkv[(size_t)row * QKV_N + QSIZE + c4];
        int tb = row >> 3, g = row & 7;
        int kk = d4 >> 4;
        int word = (d4 >> 3) & 1;
        int t0 = (d4 & 7) >> 1;
        unsigned* dst = g_kf16 +
            ((((size_t)(kvh * 512 + tb) * 4 + kk) * 32 + g * 4 + t0) << 1) + word;
        dst[0] = pack_h2(v.x, v.y);
        dst[2] = pack_h2(v.z, v.w);
    }

    // --- V: float4 over d (4 scalar half stores; tiny tensor) ---
    for (int i = tid0; i < S_LEN * KVSIZE / 4; i += stride) {
        int row = i >> 6;                 // kv position t
        int c4  = (i & 63) * 4;
        int kvh = c4 >> 6, d4 = c4 & 63;
        float4 v = *(const float4*)&g_qkv[(size_t)row * QKV_N + QSIZE + KVSIZE + c4];
        float vv[4] = {v.x, v.y, v.z, v.w};
        int t16 = row >> 4, rem = row & 15;
        int word = (rem >> 3) & 1;
        int t = (rem & 7) >> 1;
        int half = rem & 1;
        int nt = d4 >> 3;
        __half* vh = (__half*)g_vf16;
#pragma unroll
        for (int e = 0; e < 4; e++) {
            int g = (d4 & 7) + e;
            size_t a = (((((size_t)(kvh * 256 + t16) * 8 + nt) * 32 + g * 4 + t) << 1)
                        + word) * 2 + half;
            vh[a] = __float2half_rn(vv[e]);
        }
    }
}

// ---------------------------------------------------------------------------
// Causal GQA flash attention, fp16 mma m16n8k16, no smem/barriers.
// LPT: qb = gridDim.x-1-blockIdx.x. Ping-pong register prefetch of B frags.
// P C-frag -> A-frag is pure register packing (no shuffles).
// ---------------------------------------------------------------------------
__global__ __launch_bounds__(128, 3) void flash_tc_kernel()
{
    const int lane = threadIdx.x & 31;
    const int warp = threadIdx.x >> 5;
    const int qb = (int)gridDim.x - 1 - (int)blockIdx.x;
    const int h  = blockIdx.y;
    const int kvh = h >> 2;

    const int gq = lane >> 2;
    const int tq = lane & 3;

    // Q fragments (scale folded): qa[kk][4]
    unsigned qa[4][4];
    {
        const uint4* qf = (const uint4*)g_qf16 +
            ((size_t)(h * 256 + qb * 4 + warp) * 4) * 32;
#pragma unroll
        for (int kk = 0; kk < 4; kk++)
            *(uint4*)qa[kk] = qf[kk * 32 + lane];
    }

    float m_s[2] = {-1e30f, -1e30f};
    float l_s[2] = {0.f, 0.f};
    float acc_o[8][4];
#pragma unroll
    for (int i = 0; i < 8; i++)
#pragma unroll
        for (int j = 0; j < 4; j++) acc_o[i][j] = 0.f;

    const int qrow0 = (warp << 4) + gq;

    const uint2* kf0 = (const uint2*)g_kf16 + ((size_t)kvh * 512 * 4) * 32;
    const uint2* vf0 = (const uint2*)g_vf16 + ((size_t)kvh * 256 * 8) * 32;

    uint2 buf[2][8];
    // preload K(kb=0, kk=0): index ((nt)*4 + 0)*32 + lane
#pragma unroll
    for (int nt = 0; nt < 8; nt++)
        buf[0][nt] = kf0[((nt << 2)) * 32 + lane];

    for (int kb = 0; kb <= qb; kb++) {
        const uint2* kf = kf0 + ((size_t)(kb * 8) * 4) * 32;   // [nt][kk][lane]
        const uint2* vf = vf0 + ((size_t)(kb * 4) * 8) * 32;   // [kk][nt][lane]

        // ---- S = (Q*scale) @ K^T : 4 ksteps (d) x 8 ntiles (kv) ----
        float s[8][4];
#pragma unroll
        for (int nt = 0; nt < 8; nt++)
#pragma unroll
            for (int j = 0; j < 4; j++) s[nt][j] = 0.f;
#pragma unroll
        for (int kk = 0; kk < 4; kk++) {
            const int cur = kk & 1, nxt = cur ^ 1;
            if (kk < 3) {
#pragma unroll
                for (int nt = 0; nt < 8; nt++)
                    buf[nxt][nt] = kf[((nt << 2) | (kk + 1)) * 32 + lane];
            } else {
                // prefetch V(kb, kk=0)
#pragma unroll
                for (int nt = 0; nt < 8; nt++)
                    buf[nxt][nt] = vf[nt * 32 + lane];
            }
#pragma unroll
            for (int nt = 0; nt < 8; nt++)
                mma_f16(s[nt], qa[kk], (const unsigned*)&buf[cur][nt]);
        }

        // ---- causal mask on diagonal tile ----
        if (kb == qb) {
#pragma unroll
            for (int nt = 0; nt < 8; nt++) {
                int cb = (nt << 3) + (tq << 1);
                if (cb     > qrow0)     s[nt][0] = -1e30f;
                if (cb + 1 > qrow0)     s[nt][1] = -1e30f;
                if (cb     > qrow0 + 8) s[nt][2] = -1e30f;
                if (cb + 1 > qrow0 + 8) s[nt][3] = -1e30f;
            }
        }

        // ---- online softmax (V kk=0 loads in flight underneath) ----
        float mx0 = -1e30f, mx1 = -1e30f;
#pragma unroll
        for (int nt = 0; nt < 8; nt++) {
            mx0 = fmaxf(mx0, fmaxf(s[nt][0], s[nt][1]));
            mx1 = fmaxf(mx1, fmaxf(s[nt][2], s[nt][3]));
        }
        mx0 = fmaxf(mx0, __shfl_xor_sync(0xffffffffu, mx0, 1));
        mx0 = fmaxf(mx0, __shfl_xor_sync(0xffffffffu, mx0, 2));
        mx1 = fmaxf(mx1, __shfl_xor_sync(0xffffffffu, mx1, 1));
        mx1 = fmaxf(mx1, __shfl_xor_sync(0xffffffffu, mx1, 2));
        float nm0 = fmaxf(m_s[0], mx0), nm1 = fmaxf(m_s[1], mx1);
        float al0 = __expf(m_s[0] - nm0), al1 = __expf(m_s[1] - nm1);
        m_s[0] = nm0; m_s[1] = nm1;

        float sum0 = 0.f, sum1 = 0.f;
#pragma unroll
        for (int nt = 0; nt < 8; nt++) {
            s[nt][0] = __expf(s[nt][0] - nm0);
            s[nt][1] = __expf(s[nt][1] - nm0);
            s[nt][2] = __expf(s[nt][2] - nm1);
            s[nt][3] = __expf(s[nt][3] - nm1);
            sum0 += s[nt][0] + s[nt][1];
            sum1 += s[nt][2] + s[nt][3];
        }
        sum0 += __shfl_xor_sync(0xffffffffu, sum0, 1);
        sum0 += __shfl_xor_sync(0xffffffffu, sum0, 2);
        sum1 += __shfl_xor_sync(0xffffffffu, sum1, 1);
        sum1 += __shfl_xor_sync(0xffffffffu, sum1, 2);
        l_s[0] = l_s[0] * al0 + sum0;
        l_s[1] = l_s[1] * al1 + sum1;

#pragma unroll
        for (int nt = 0; nt < 8; nt++) {
            acc_o[nt][0] *= al0; acc_o[nt][1] *= al0;
            acc_o[nt][2] *= al1; acc_o[nt][3] *= al1;
        }

        // ---- PV: 4 ksteps (kv, k16) x 8 ntiles (HD); P packed in-register ----
        const bool more = (kb < qb);
        const uint2* kf_next = kf + (8 * 4) * 32;
#pragma unroll
        for (int kk = 0; kk < 4; kk++) {
            const int cur = kk & 1, nxt = cur ^ 1;
            if (kk < 3) {
#pragma unroll
                for (int nt = 0; nt < 8; nt++)
                    buf[nxt][nt] = vf[(((kk + 1) << 3) | nt) * 32 + lane];
            } else if (more) {
#pragma unroll
                for (int nt = 0; nt < 8; nt++)
                    buf[nxt][nt] = kf_next[((nt << 2)) * 32 + lane];
            }
            unsigned pa[4];
            pa[0] = pack_h2(s[2 * kk][0],     s[2 * kk][1]);
            pa[1] = pack_h2(s[2 * kk][2],     s[2 * kk][3]);
            pa[2] = pack_h2(s[2 * kk + 1][0], s[2 * kk + 1][1]);
            pa[3] = pack_h2(s[2 * kk + 1][2], s[2 * kk + 1][3]);
#pragma unroll
            for (int nt = 0; nt < 8; nt++)
                mma_f16(acc_o[nt], pa, (const unsigned*)&buf[cur][nt]);
        }
    }

    // ---- normalize + write ----
    float inv0 = 1.0f / l_s[0];
    float inv1 = 1.0f / l_s[1];
    int row0 = qb * 64 + (warp << 4) + gq;
#pragma unroll
    for (int nt = 0; nt < 8; nt++) {
        int col = h * HD + (nt << 3) + (tq << 1);
        float2 lo = {acc_o[nt][0] * inv0, acc_o[nt][1] * inv0};
        float2 hi = {acc_o[nt][2] * inv1, acc_o[nt][3] * inv1};
        *(float2*)(g_attn + (size_t)row0 * QSIZE + col)       = lo;
        *(float2*)(g_attn + (size_t)(row0 + 8) * QSIZE + col) = hi;
    }
}

// ---------------------------------------------------------------------------
extern "C" void kernel_launch(void* const* d_in, const int* in_sizes, int n_in,
                              void* d_out, int out_size)
{
    const int*   positions = (const int*)d_in[0];
    const float* hidden    = (const float*)d_in[1];
    const float* w_qkv     = (const float*)d_in[2];
    const float* w_o       = (const float*)d_in[3];
    float*       out       = (float*)d_out;

    float* qkv = nullptr;
    float* attn = nullptr;
    cudaGetSymbolAddress((void**)&qkv, g_qkv);
    cudaGetSymbolAddress((void**)&attn, g_attn);

    // 1) qkv = hidden @ w_qkv^T
    gemm_nt_kernel<<<dim3(QKV_N / 128, S_LEN / 128), 256>>>(
        hidden, w_qkv, qkv, S_LEN, QKV_N, IN_DIM);

    // 2) RoPE in place on q,k
    const int rope_total = S_LEN * (NH + NKV) * 32;
    rope_kernel<<<(rope_total + 255) / 256, 256>>>(positions);

    // 3) one-time fragment conversion (Q,K,V -> fp16 mma layouts)
    convert_frag_kernel<<<1024, 256>>>();

    // 4) causal GQA flash attention (fp16 tensor cores, no smem)
    flash_tc_kernel<<<dim3(S_LEN / 64, NH), 128>>>();

    // 5) out = attn @ w_o^T
    gemm_nt_kernel<<<dim3(HID / 128, S_LEN / 128), 256>>>(
        attn, w_o, out, S_LEN, HID, QSIZE);
}

// round 8
// speedup vs baseline: 2.4757x; 1.0602x over previous
#include <cuda_runtime.h>
#include <cuda_fp16.h>
#include <math.h>

#define S_LEN  4096
#define NH     16
#define NKV    4
#define HD     64
#define QSIZE  1024      // NH*HD
#define KVSIZE 256       // NKV*HD
#define QKV_N  1536      // QSIZE + 2*KVSIZE
#define IN_DIM 2048      // 2*HID
#define HID    1024

// Scratch (device globals; no allocations allowed)
__device__ float g_qkv[S_LEN * QKV_N];        // 25.2 MB
__device__ float g_attn[S_LEN * QSIZE];       // 16.8 MB
// fp16 fragment-major tensors for mma.sync m16n8k16
__device__ unsigned g_qf16[16 * 256 * 4 * 32 * 4]; // 8.4 MB : [h][mt][kk][lane][4]
__device__ unsigned g_kf16[4 * 512 * 4 * 32 * 2];  // 2.1 MB : [kvh][tb][kk][lane][2]
__device__ unsigned g_vf16[4 * 256 * 8 * 32 * 2];  // 2.1 MB : [kvh][t16][nt][lane][2]

// ---------------------------------------------------------------------------
// Generic NT SGEMM (fp32):  C[M,N] = A[M,K] @ B[N,K]^T
// ---------------------------------------------------------------------------
__global__ __launch_bounds__(256) void gemm_nt_kernel(
    const float* __restrict__ A, const float* __restrict__ B,
    float* __restrict__ C, int M, int N, int K)
{
    __shared__ float As[16][128];
    __shared__ float Bs[16][128];
    const int tid = threadIdx.x;
    const int tx = tid & 15;
    const int ty = tid >> 4;
    const int m0 = blockIdx.y * 128;
    const int n0 = blockIdx.x * 128;

    float acc[8][8];
#pragma unroll
    for (int i = 0; i < 8; i++)
#pragma unroll
        for (int j = 0; j < 8; j++) acc[i][j] = 0.f;

    for (int k0 = 0; k0 < K; k0 += 16) {
#pragma unroll
        for (int l = 0; l < 2; l++) {
            int idx = tid * 2 + l;
            int row = idx >> 2;
            int kq  = (idx & 3) * 4;
            float4 va = *(const float4*)(A + (size_t)(m0 + row) * K + k0 + kq);
            As[kq + 0][row] = va.x; As[kq + 1][row] = va.y;
            As[kq + 2][row] = va.z; As[kq + 3][row] = va.w;
            float4 vb = *(const float4*)(B + (size_t)(n0 + row) * K + k0 + kq);
            Bs[kq + 0][row] = vb.x; Bs[kq + 1][row] = vb.y;
            Bs[kq + 2][row] = vb.z; Bs[kq + 3][row] = vb.w;
        }
        __syncthreads();
#pragma unroll
        for (int kk = 0; kk < 16; kk++) {
            float a[8], b[8];
            *(float4*)&a[0] = *(const float4*)&As[kk][ty * 8];
            *(float4*)&a[4] = *(const float4*)&As[kk][ty * 8 + 4];
            *(float4*)&b[0] = *(const float4*)&Bs[kk][tx * 8];
            *(float4*)&b[4] = *(const float4*)&Bs[kk][tx * 8 + 4];
#pragma unroll
            for (int i = 0; i < 8; i++)
#pragma unroll
                for (int j = 0; j < 8; j++)
                    acc[i][j] = fmaf(a[i], b[j], acc[i][j]);
        }
        __syncthreads();
    }
#pragma unroll
    for (int i = 0; i < 8; i++) {
        float* crow = C + (size_t)(m0 + ty * 8 + i) * N + n0 + tx * 8;
        float4 v0 = {acc[i][0], acc[i][1], acc[i][2], acc[i][3]};
        float4 v1 = {acc[i][4], acc[i][5], acc[i][6], acc[i][7]};
        *(float4*)(crow)     = v0;
        *(float4*)(crow + 4) = v1;
    }
}

// ---------------------------------------------------------------------------
// RoPE (phase fp32, matching the reference; inv_freq table in fp64 per block)
// ---------------------------------------------------------------------------
__global__ void rope_kernel(const int* __restrict__ positions)
{
    __shared__ float invf_s[32];
    int tid = threadIdx.x;
    if (tid < 32)
        invf_s[tid] = (float)exp(-(double)tid * (1.0 / 32.0) * log(10000.0));
    __syncthreads();

    int idx = blockIdx.x * blockDim.x + tid;
    const int total = S_LEN * (NH + NKV) * 32;
    if (idx >= total) return;
    int j = idx & 31;
    int h = (idx >> 5) % (NH + NKV);
    int s = idx / (32 * (NH + NKV));
    int off = (h < NH) ? h * HD : QSIZE + (h - NH) * HD;
    float* base = g_qkv + (size_t)s * QKV_N + off;

    float f = (float)positions[s] * invf_s[j];
    float sn, c;
    sincosf(f, &sn, &c);
    float x1 = base[j], x2 = base[j + 32];
    base[j]      = x1 * c - x2 * sn;
    base[j + 32] = x2 * c + x1 * sn;
}

// ---------------------------------------------------------------------------
// fp16 mma helpers
// ---------------------------------------------------------------------------
__device__ __forceinline__ void mma_f16(float* c, const unsigned* a, const unsigned* b) {
    asm volatile(
        "mma.sync.aligned.m16n8k16.row.col.f32.f16.f16.f32 "
        "{%0,%1,%2,%3}, {%4,%5,%6,%7}, {%8,%9}, {%0,%1,%2,%3};"
        : "+f"(c[0]), "+f"(c[1]), "+f"(c[2]), "+f"(c[3])
        : "r"(a[0]), "r"(a[1]), "r"(a[2]), "r"(a[3]), "r"(b[0]), "r"(b[1]));
}

__device__ __forceinline__ unsigned pack_h2(float lo, float hi) {
    __half2 h = __floats2half2_rn(lo, hi);
    return *(unsigned*)&h;
}

// ---------------------------------------------------------------------------
// One-time fragment conversion, WARP-PER-FRAGMENT-TILE:
// lanes are laid out exactly as the mma fragment expects, so every store is
// a lane-contiguous STG.128/STG.64 and every gather instruction reads
// 8 rows x 32B-contiguous spans (no transaction amplification).
// Units: Q 4096 (h,mt) | K 2048 (kvh,tb) | V 1024 (kvh,t16) = 7168 warps.
// ---------------------------------------------------------------------------
__global__ __launch_bounds__(256) void convert_frag_kernel()
{
    const int wid  = (blockIdx.x * blockDim.x + threadIdx.x) >> 5;
    const int lane = threadIdx.x & 31;
    const int g = lane >> 2, t = lane & 3;

    if (wid < 4096) {
        // ---- Q unit: h = wid>>8, mt = wid&255 ; scale 1/8 folded ----
        const int h = wid >> 8, mt = wid & 255;
        const float* Q = g_qkv + (size_t)(mt * 16) * QKV_N + h * 64;
        unsigned* dst = g_qf16 + ((size_t)(h * 256 + mt) * 4) * 128;
#pragma unroll
        for (int kk = 0; kk < 4; kk++) {
            int c = kk * 16 + 2 * t;
            float2 a0 = *(const float2*)(Q + (size_t)g * QKV_N + c);
            float2 a1 = *(const float2*)(Q + (size_t)(g + 8) * QKV_N + c);
            float2 a2 = *(const float2*)(Q + (size_t)g * QKV_N + c + 8);
            float2 a3 = *(const float2*)(Q + (size_t)(g + 8) * QKV_N + c + 8);
            uint4 w;
            w.x = pack_h2(a0.x * 0.125f, a0.y * 0.125f);
            w.y = pack_h2(a1.x * 0.125f, a1.y * 0.125f);
            w.z = pack_h2(a2.x * 0.125f, a2.y * 0.125f);
            w.w = pack_h2(a3.x * 0.125f, a3.y * 0.125f);
            *(uint4*)(dst + ((kk * 32 + lane) << 2)) = w;
        }
    } else if (wid < 4096 + 2048) {
        // ---- K unit: b0 = {K[tb*8+g][c], K[..][c+1]}, b1 = cols +8 ----
        const int u = wid - 4096;
        const int kvh = u >> 9, tb = u & 511;
        const float* K = g_qkv + (size_t)(tb * 8 + g) * QKV_N + QSIZE + kvh * 64;
        unsigned* dst = g_kf16 + ((size_t)(kvh * 512 + tb) * 4) * 64;
#pragma unroll
        for (int kk = 0; kk < 4; kk++) {
            int c = kk * 16 + 2 * t;
            float2 b0 = *(const float2*)(K + c);
            float2 b1 = *(const float2*)(K + c + 8);
            uint2 w;
            w.x = pack_h2(b0.x, b0.y);
            w.y = pack_h2(b1.x, b1.y);
            *(uint2*)(dst + ((kk * 32 + lane) << 1)) = w;
        }
    } else if (wid < 4096 + 2048 + 1024) {
        // ---- V unit: b0 = {V[2t][d], V[2t+1][d]}, b1 = rows +8 ----
        const int u = wid - 4096 - 2048;
        const int kvh = u >> 8, t16 = u & 255;
        const float* V = g_qkv + (size_t)(t16 * 16) * QKV_N + QSIZE + KVSIZE + kvh * 64;
        unsigned* dst = g_vf16 + ((size_t)(kvh * 256 + t16) * 8) * 64;
#pragma unroll
        for (int nt = 0; nt < 8; nt++) {
            int d = nt * 8 + g;
            float v0 = V[(size_t)(2 * t) * QKV_N + d];
            float v1 = V[(size_t)(2 * t + 1) * QKV_N + d];
            float v2 = V[(size_t)(2 * t + 8) * QKV_N + d];
            float v3 = V[(size_t)(2 * t + 9) * QKV_N + d];
            uint2 w;
            w.x = pack_h2(v0, v1);
            w.y = pack_h2(v2, v3);
            *(uint2*)(dst + ((nt * 32 + lane) << 1)) = w;
        }
    }
}

// ---------------------------------------------------------------------------
// Causal GQA flash attention, fp16 mma m16n8k16, no smem/barriers.
// LPT: qb = gridDim.x-1-blockIdx.x. Ping-pong register prefetch of B frags.
// P C-frag -> A-frag is pure register packing (no shuffles).
// ---------------------------------------------------------------------------
__global__ __launch_bounds__(128, 3) void flash_tc_kernel()
{
    const int lane = threadIdx.x & 31;
    const int warp = threadIdx.x >> 5;
    const int qb = (int)gridDim.x - 1 - (int)blockIdx.x;
    const int h  = blockIdx.y;
    const int kvh = h >> 2;

    const int gq = lane >> 2;
    const int tq = lane & 3;

    // Q fragments (scale folded): qa[kk][4]
    unsigned qa[4][4];
    {
        const uint4* qf = (const uint4*)g_qf16 +
            ((size_t)(h * 256 + qb * 4 + warp) * 4) * 32;
#pragma unroll
        for (int kk = 0; kk < 4; kk++)
            *(uint4*)qa[kk] = qf[kk * 32 + lane];
    }

    float m_s[2] = {-1e30f, -1e30f};
    float l_s[2] = {0.f, 0.f};
    float acc_o[8][4];
#pragma unroll
    for (int i = 0; i < 8; i++)
#pragma unroll
        for (int j = 0; j < 4; j++) acc_o[i][j] = 0.f;

    const int qrow0 = (warp << 4) + gq;

    const uint2* kf0 = (const uint2*)g_kf16 + ((size_t)kvh * 512 * 4) * 32;
    const uint2* vf0 = (const uint2*)g_vf16 + ((size_t)kvh * 256 * 8) * 32;

    uint2 buf[2][8];
    // preload K(kb=0, kk=0)
#pragma unroll
    for (int nt = 0; nt < 8; nt++)
        buf[0][nt] = kf0[((nt << 2)) * 32 + lane];

    for (int kb = 0; kb <= qb; kb++) {
        const uint2* kf = kf0 + ((size_t)(kb * 8) * 4) * 32;   // [nt][kk][lane]
        const uint2* vf = vf0 + ((size_t)(kb * 4) * 8) * 32;   // [kk][nt][lane]

        // ---- S = (Q*scale) @ K^T : 4 ksteps (d) x 8 ntiles (kv) ----
        float s[8][4];
#pragma unroll
        for (int nt = 0; nt < 8; nt++)
#pragma unroll
            for (int j = 0; j < 4; j++) s[nt][j] = 0.f;
#pragma unroll
        for (int kk = 0; kk < 4; kk++) {
            const int cur = kk & 1, nxt = cur ^ 1;
            if (kk < 3) {
#pragma unroll
                for (int nt = 0; nt < 8; nt++)
                    buf[nxt][nt] = kf[((nt << 2) | (kk + 1)) * 32 + lane];
            } else {
                // prefetch V(kb, kk=0)
#pragma unroll
                for (int nt = 0; nt < 8; nt++)
                    buf[nxt][nt] = vf[nt * 32 + lane];
            }
#pragma unroll
            for (int nt = 0; nt < 8; nt++)
                mma_f16(s[nt], qa[kk], (const unsigned*)&buf[cur][nt]);
        }

        // ---- causal mask on diagonal tile ----
        if (kb == qb) {
#pragma unroll
            for (int nt = 0; nt < 8; nt++) {
                int cb = (nt << 3) + (tq << 1);
                if (cb     > qrow0)     s[nt][0] = -1e30f;
                if (cb + 1 > qrow0)     s[nt][1] = -1e30f;
                if (cb     > qrow0 + 8) s[nt][2] = -1e30f;
                if (cb + 1 > qrow0 + 8) s[nt][3] = -1e30f;
            }
        }

        // ---- online softmax (V kk=0 loads in flight underneath) ----
        float mx0 = -1e30f, mx1 = -1e30f;
#pragma unroll
        for (int nt = 0; nt < 8; nt++) {
            mx0 = fmaxf(mx0, fmaxf(s[nt][0], s[nt][1]));
            mx1 = fmaxf(mx1, fmaxf(s[nt][2], s[nt][3]));
        }
        mx0 = fmaxf(mx0, __shfl_xor_sync(0xffffffffu, mx0, 1));
        mx0 = fmaxf(mx0, __shfl_xor_sync(0xffffffffu, mx0, 2));
        mx1 = fmaxf(mx1, __shfl_xor_sync(0xffffffffu, mx1, 1));
        mx1 = fmaxf(mx1, __shfl_xor_sync(0xffffffffu, mx1, 2));
        float nm0 = fmaxf(m_s[0], mx0), nm1 = fmaxf(m_s[1], mx1);
        float al0 = __expf(m_s[0] - nm0), al1 = __expf(m_s[1] - nm1);
        m_s[0] = nm0; m_s[1] = nm1;

        float sum0 = 0.f, sum1 = 0.f;
#pragma unroll
        for (int nt = 0; nt < 8; nt++) {
            s[nt][0] = __expf(s[nt][0] - nm0);
            s[nt][1] = __expf(s[nt][1] - nm0);
            s[nt][2] = __expf(s[nt][2] - nm1);
            s[nt][3] = __expf(s[nt][3] - nm1);
            sum0 += s[nt][0] + s[nt][1];
            sum1 += s[nt][2] + s[nt][3];
        }
        sum0 += __shfl_xor_sync(0xffffffffu, sum0, 1);
        sum0 += __shfl_xor_sync(0xffffffffu, sum0, 2);
        sum1 += __shfl_xor_sync(0xffffffffu, sum1, 1);
        sum1 += __shfl_xor_sync(0xffffffffu, sum1, 2);
        l_s[0] = l_s[0] * al0 + sum0;
        l_s[1] = l_s[1] * al1 + sum1;

#pragma unroll
        for (int nt = 0; nt < 8; nt++) {
            acc_o[nt][0] *= al0; acc_o[nt][1] *= al0;
            acc_o[nt][2] *= al1; acc_o[nt][3] *= al1;
        }

        // ---- PV: 4 ksteps (kv, k16) x 8 ntiles (HD); P packed in-register ----
        const bool more = (kb < qb);
        const uint2* kf_next = kf + (8 * 4) * 32;
#pragma unroll
        for (int kk = 0; kk < 4; kk++) {
            const int cur = kk & 1, nxt = cur ^ 1;
            if (kk < 3) {
#pragma unroll
                for (int nt = 0; nt < 8; nt++)
                    buf[nxt][nt] = vf[(((kk + 1) << 3) | nt) * 32 + lane];
            } else if (more) {
#pragma unroll
                for (int nt = 0; nt < 8; nt++)
                    buf[nxt][nt] = kf_next[((nt << 2)) * 32 + lane];
            }
            unsigned pa[4];
            pa[0] = pack_h2(s[2 * kk][0],     s[2 * kk][1]);
            pa[1] = pack_h2(s[2 * kk][2],     s[2 * kk][3]);
            pa[2] = pack_h2(s[2 * kk + 1][0], s[2 * kk + 1][1]);
            pa[3] = pack_h2(s[2 * kk + 1][2], s[2 * kk + 1][3]);
#pragma unroll
            for (int nt = 0; nt < 8; nt++)
                mma_f16(acc_o[nt], pa, (const unsigned*)&buf[cur][nt]);
        }
    }

    // ---- normalize + write ----
    float inv0 = 1.0f / l_s[0];
    float inv1 = 1.0f / l_s[1];
    int row0 = qb * 64 + (warp << 4) + gq;
#pragma unroll
    for (int nt = 0; nt < 8; nt++) {
        int col = h * HD + (nt << 3) + (tq << 1);
        float2 lo = {acc_o[nt][0] * inv0, acc_o[nt][1] * inv0};
        float2 hi = {acc_o[nt][2] * inv1, acc_o[nt][3] * inv1};
        *(float2*)(g_attn + (size_t)row0 * QSIZE + col)       = lo;
        *(float2*)(g_attn + (size_t)(row0 + 8) * QSIZE + col) = hi;
    }
}

// ---------------------------------------------------------------------------
extern "C" void kernel_launch(void* const* d_in, const int* in_sizes, int n_in,
                              void* d_out, int out_size)
{
    const int*   positions = (const int*)d_in[0];
    const float* hidden    = (const float*)d_in[1];
    const float* w_qkv     = (const float*)d_in[2];
    const float* w_o       = (const float*)d_in[3];
    float*       out       = (float*)d_out;

    float* qkv = nullptr;
    float* attn = nullptr;
    cudaGetSymbolAddress((void**)&qkv, g_qkv);
    cudaGetSymbolAddress((void**)&attn, g_attn);

    // 1) qkv = hidden @ w_qkv^T
    gemm_nt_kernel<<<dim3(QKV_N / 128, S_LEN / 128), 256>>>(
        hidden, w_qkv, qkv, S_LEN, QKV_N, IN_DIM);

    // 2) RoPE in place on q,k
    const int rope_total = S_LEN * (NH + NKV) * 32;
    rope_kernel<<<(rope_total + 255) / 256, 256>>>(positions);

    // 3) one-time fragment conversion (warp-per-tile, coalesced both ways)
    convert_frag_kernel<<<(7168 * 32) / 256, 256>>>();

    // 4) causal GQA flash attention (fp16 tensor cores, no smem)
    flash_tc_kernel<<<dim3(S_LEN / 64, NH), 128>>>();

    // 5) out = attn @ w_o^T
    gemm_nt_kernel<<<dim3(HID / 128, S_LEN / 128), 256>>>(
        attn, w_o, out, S_LEN, HID, QSIZE);
}

// round 9
// speedup vs baseline: 5.4730x; 2.2107x over previous
#include <cuda_runtime.h>
#include <cuda_fp16.h>
#include <math.h>

#define S_LEN  4096
#define NH     16
#define NKV    4
#define HD     64
#define QSIZE  1024      // NH*HD
#define KVSIZE 256       // NKV*HD
#define QKV_N  1536      // QSIZE + 2*KVSIZE
#define IN_DIM 2048      // 2*HID
#define HID    1024

// Scratch (device globals; no allocations allowed)
__device__ float g_qkv[S_LEN * QKV_N];             // 25.2 MB
// flash fp16 fragment tensors
__device__ unsigned g_qf16[16 * 256 * 4 * 32 * 4]; // [h][mt][kk][lane][4]
__device__ unsigned g_kf16[4 * 512 * 4 * 32 * 2];  // [kvh][tb][kk][lane][2]
__device__ unsigned g_vf16[4 * 256 * 8 * 32 * 2];  // [kvh][t16][nt][lane][2]
// split-fp16 GEMM operand fragments
__device__ uint4 g_hid_h[256 * 128 * 32];          // hidden A-frag hi [mt][kk][lane]
__device__ uint4 g_hid_l[256 * 128 * 32];          //                lo
__device__ uint2 g_wqkv_h[192 * 128 * 32];         // w_qkv B-frag hi [nt][kk][lane]
__device__ uint2 g_wqkv_l[192 * 128 * 32];
__device__ uint2 g_wo_h[128 * 64 * 32];            // w_o B-frag hi [nt][kk][lane]
__device__ uint2 g_wo_l[128 * 64 * 32];
__device__ uint4 g_attn_h[256 * 64 * 32];          // attn A-frag hi [mt][kk][lane]
__device__ uint4 g_attn_l[256 * 64 * 32];

// ---------------------------------------------------------------------------
// helpers
// ---------------------------------------------------------------------------
__device__ __forceinline__ void mma_f16(float* c, const unsigned* a, const unsigned* b) {
    asm volatile(
        "mma.sync.aligned.m16n8k16.row.col.f32.f16.f16.f32 "
        "{%0,%1,%2,%3}, {%4,%5,%6,%7}, {%8,%9}, {%0,%1,%2,%3};"
        : "+f"(c[0]), "+f"(c[1]), "+f"(c[2]), "+f"(c[3])
        : "r"(a[0]), "r"(a[1]), "r"(a[2]), "r"(a[3]), "r"(b[0]), "r"(b[1]));
}

__device__ __forceinline__ unsigned pack_h2(float lo, float hi) {
    __half2 h = __floats2half2_rn(lo, hi);
    return *(unsigned*)&h;
}

// split x -> (hi, lo) fp16 pair packed as two h2 words
__device__ __forceinline__ void split_h2(float a, float b, unsigned& hi, unsigned& lo) {
    __half ha = __float2half_rn(a), hb = __float2half_rn(b);
    float ra = a - __half2float(ha), rb = b - __half2float(hb);
    __half2 h = __halves2half2(ha, hb);
    hi = *(unsigned*)&h;
    lo = pack_h2(ra, rb);
}

// ---------------------------------------------------------------------------
// RoPE (phase fp32 matching reference; inv_freq table fp64 per block)
// ---------------------------------------------------------------------------
__global__ void rope_kernel(const int* __restrict__ positions)
{
    __shared__ float invf_s[32];
    int tid = threadIdx.x;
    if (tid < 32)
        invf_s[tid] = (float)exp(-(double)tid * (1.0 / 32.0) * log(10000.0));
    __syncthreads();

    int idx = blockIdx.x * blockDim.x + tid;
    const int total = S_LEN * (NH + NKV) * 32;
    if (idx >= total) return;
    int j = idx & 31;
    int h = (idx >> 5) % (NH + NKV);
    int s = idx / (32 * (NH + NKV));
    int off = (h < NH) ? h * HD : QSIZE + (h - NH) * HD;
    float* base = g_qkv + (size_t)s * QKV_N + off;

    float f = (float)positions[s] * invf_s[j];
    float sn, c;
    sincosf(f, &sn, &c);
    float x1 = base[j], x2 = base[j + 32];
    base[j]      = x1 * c - x2 * sn;
    base[j + 32] = x2 * c + x1 * sn;
}

// ---------------------------------------------------------------------------
// Convert INPUTS to split-fp16 fragments (warp-per-tile; coalesced both ways).
// units: hidden A 256*128=32768 | w_qkv B 192*128=24576 | w_o B 128*64=8192
// ---------------------------------------------------------------------------
__global__ __launch_bounds__(256) void convert_in_kernel(
    const float* __restrict__ hidden, const float* __restrict__ w_qkv,
    const float* __restrict__ w_o)
{
    const int wid  = (blockIdx.x * blockDim.x + threadIdx.x) >> 5;
    const int lane = threadIdx.x & 31;
    const int g = lane >> 2, t = lane & 3;

    if (wid < 32768) {
        const int mt = wid >> 7, kk = wid & 127;
        const float* A = hidden + (size_t)(mt * 16) * IN_DIM + kk * 16;
        float2 a0 = *(const float2*)(A + (size_t)g * IN_DIM + 2 * t);
        float2 a1 = *(const float2*)(A + (size_t)(g + 8) * IN_DIM + 2 * t);
        float2 a2 = *(const float2*)(A + (size_t)g * IN_DIM + 2 * t + 8);
        float2 a3 = *(const float2*)(A + (size_t)(g + 8) * IN_DIM + 2 * t + 8);
        uint4 h, l;
        split_h2(a0.x, a0.y, h.x, l.x);
        split_h2(a1.x, a1.y, h.y, l.y);
        split_h2(a2.x, a2.y, h.z, l.z);
        split_h2(a3.x, a3.y, h.w, l.w);
        size_t o = (size_t)wid * 32 + lane;
        g_hid_h[o] = h; g_hid_l[o] = l;
    } else if (wid < 32768 + 24576) {
        const int u = wid - 32768;
        const int nt = u >> 7, kk = u & 127;
        const float* B = w_qkv + (size_t)(nt * 8 + g) * IN_DIM + kk * 16;
        float2 b0 = *(const float2*)(B + 2 * t);
        float2 b1 = *(const float2*)(B + 2 * t + 8);
        uint2 h, l;
        split_h2(b0.x, b0.y, h.x, l.x);
        split_h2(b1.x, b1.y, h.y, l.y);
        size_t o = (size_t)u * 32 + lane;
        g_wqkv_h[o] = h; g_wqkv_l[o] = l;
    } else {
        const int u = wid - 32768 - 24576;
        const int nt = u >> 6, kk = u & 63;
        const float* B = w_o + (size_t)(nt * 8 + g) * QSIZE + kk * 16;
        float2 b0 = *(const float2*)(B + 2 * t);
        float2 b1 = *(const float2*)(B + 2 * t + 8);
        uint2 h, l;
        split_h2(b0.x, b0.y, h.x, l.x);
        split_h2(b1.x, b1.y, h.y, l.y);
        size_t o = (size_t)u * 32 + lane;
        g_wo_h[o] = h; g_wo_l[o] = l;
    }
}

// ---------------------------------------------------------------------------
// Split-fp16 NT GEMM on fragment-major operands:
//   C[M,N] = Ah@Bh^T + Ah@Bl^T + Al@Bh^T   (fp32 accumulate, fp32 C out)
// grid (N/128, M/128), 256 thr = 8 warps; warp tile 64(M) x 32(N).
// No smem/barriers; ping-pong register prefetch over k16 slabs.
// ---------------------------------------------------------------------------
__global__ __launch_bounds__(256, 1) void gemm_frag_kernel(
    const uint4* __restrict__ Ah, const uint4* __restrict__ Al,
    const uint2* __restrict__ Bh, const uint2* __restrict__ Bl,
    float* __restrict__ C, int Nn, int Kk)
{
    const int lane = threadIdx.x & 31;
    const int w = threadIdx.x >> 5;
    const int mt0 = blockIdx.y * 8 + (w >> 2) * 4;
    const int nt0 = blockIdx.x * 16 + (w & 3) * 4;

    const uint4 *pah[4], *pal[4];
    const uint2 *pbh[4], *pbl[4];
#pragma unroll
    for (int i = 0; i < 4; i++) {
        size_t oa = ((size_t)(mt0 + i) * Kk) * 32 + lane;
        size_t ob = ((size_t)(nt0 + i) * Kk) * 32 + lane;
        pah[i] = Ah + oa; pal[i] = Al + oa;
        pbh[i] = Bh + ob; pbl[i] = Bl + ob;
    }

    float acc[4][4][4];
#pragma unroll
    for (int i = 0; i < 4; i++)
#pragma unroll
        for (int j = 0; j < 4; j++)
#pragma unroll
            for (int e = 0; e < 4; e++) acc[i][j][e] = 0.f;

    uint4 ah[2][4], al[2][4];
    uint2 bh[2][4], bl[2][4];
#pragma unroll
    for (int i = 0; i < 4; i++) {
        ah[0][i] = pah[i][0]; al[0][i] = pal[i][0];
        bh[0][i] = pbh[i][0]; bl[0][i] = pbl[i][0];
    }

    for (int kk = 0; kk < Kk; kk++) {
        const int cur = kk & 1, nxt = cur ^ 1;
        if (kk + 1 < Kk) {
            int off = (kk + 1) * 32;
#pragma unroll
            for (int i = 0; i < 4; i++) {
                ah[nxt][i] = pah[i][off]; al[nxt][i] = pal[i][off];
                bh[nxt][i] = pbh[i][off]; bl[nxt][i] = pbl[i][off];
            }
        }
#pragma unroll
        for (int i = 0; i < 4; i++)
#pragma unroll
            for (int j = 0; j < 4; j++) {
                mma_f16(acc[i][j], (const unsigned*)&ah[cur][i], (const unsigned*)&bh[cur][j]);
                mma_f16(acc[i][j], (const unsigned*)&ah[cur][i], (const unsigned*)&bl[cur][j]);
                mma_f16(acc[i][j], (const unsigned*)&al[cur][i], (const unsigned*)&bh[cur][j]);
            }
    }

    const int g = lane >> 2, tq = lane & 3;
#pragma unroll
    for (int i = 0; i < 4; i++) {
        int r0 = (mt0 + i) * 16 + g;
#pragma unroll
        for (int j = 0; j < 4; j++) {
            int c0 = (nt0 + j) * 8 + tq * 2;
            float2 lo = {acc[i][j][0], acc[i][j][1]};
            float2 hi = {acc[i][j][2], acc[i][j][3]};
            *(float2*)(C + (size_t)r0 * Nn + c0)       = lo;
            *(float2*)(C + (size_t)(r0 + 8) * Nn + c0) = hi;
        }
    }
}

// ---------------------------------------------------------------------------
// Convert qkv (post-RoPE) to flash fp16 fragments (warp-per-tile).
// Units: Q 4096 | K 2048 | V 1024
// ---------------------------------------------------------------------------
__global__ __launch_bounds__(256) void convert_frag_kernel()
{
    const int wid  = (blockIdx.x * blockDim.x + threadIdx.x) >> 5;
    const int lane = threadIdx.x & 31;
    const int g = lane >> 2, t = lane & 3;

    if (wid < 4096) {
        const int h = wid >> 8, mt = wid & 255;
        const float* Q = g_qkv + (size_t)(mt * 16) * QKV_N + h * 64;
        unsigned* dst = g_qf16 + ((size_t)(h * 256 + mt) * 4) * 128;
#pragma unroll
        for (int kk = 0; kk < 4; kk++) {
            int c = kk * 16 + 2 * t;
            float2 a0 = *(const float2*)(Q + (size_t)g * QKV_N + c);
            float2 a1 = *(const float2*)(Q + (size_t)(g + 8) * QKV_N + c);
            float2 a2 = *(const float2*)(Q + (size_t)g * QKV_N + c + 8);
            float2 a3 = *(const float2*)(Q + (size_t)(g + 8) * QKV_N + c + 8);
            uint4 w;
            w.x = pack_h2(a0.x * 0.125f, a0.y * 0.125f);
            w.y = pack_h2(a1.x * 0.125f, a1.y * 0.125f);
            w.z = pack_h2(a2.x * 0.125f, a2.y * 0.125f);
            w.w = pack_h2(a3.x * 0.125f, a3.y * 0.125f);
            *(uint4*)(dst + ((kk * 32 + lane) << 2)) = w;
        }
    } else if (wid < 4096 + 2048) {
        const int u = wid - 4096;
        const int kvh = u >> 9, tb = u & 511;
        const float* K = g_qkv + (size_t)(tb * 8 + g) * QKV_N + QSIZE + kvh * 64;
        unsigned* dst = g_kf16 + ((size_t)(kvh * 512 + tb) * 4) * 64;
#pragma unroll
        for (int kk = 0; kk < 4; kk++) {
            int c = kk * 16 + 2 * t;
            float2 b0 = *(const float2*)(K + c);
            float2 b1 = *(const float2*)(K + c + 8);
            uint2 w;
            w.x = pack_h2(b0.x, b0.y);
            w.y = pack_h2(b1.x, b1.y);
            *(uint2*)(dst + ((kk * 32 + lane) << 1)) = w;
        }
    } else if (wid < 4096 + 2048 + 1024) {
        const int u = wid - 4096 - 2048;
        const int kvh = u >> 8, t16 = u & 255;
        const float* V = g_qkv + (size_t)(t16 * 16) * QKV_N + QSIZE + KVSIZE + kvh * 64;
        unsigned* dst = g_vf16 + ((size_t)(kvh * 256 + t16) * 8) * 64;
#pragma unroll
        for (int nt = 0; nt < 8; nt++) {
            int d = nt * 8 + g;
            float v0 = V[(size_t)(2 * t) * QKV_N + d];
            float v1 = V[(size_t)(2 * t + 1) * QKV_N + d];
            float v2 = V[(size_t)(2 * t + 8) * QKV_N + d];
            float v3 = V[(size_t)(2 * t + 9) * QKV_N + d];
            uint2 w;
            w.x = pack_h2(v0, v1);
            w.y = pack_h2(v2, v3);
            *(uint2*)(dst + ((nt * 32 + lane) << 1)) = w;
        }
    }
}

// ---------------------------------------------------------------------------
// Causal GQA flash attention, fp16 mma m16n8k16, no smem/barriers.
// Epilogue writes attn DIRECTLY as split-fp16 A-fragments for the O-proj GEMM.
// ---------------------------------------------------------------------------
__global__ __launch_bounds__(128, 3) void flash_tc_kernel()
{
    const int lane = threadIdx.x & 31;
    const int warp = threadIdx.x >> 5;
    const int qb = (int)gridDim.x - 1 - (int)blockIdx.x;   // LPT
    const int h  = blockIdx.y;
    const int kvh = h >> 2;

    const int gq = lane >> 2;
    const int tq = lane & 3;

    unsigned qa[4][4];
    {
        const uint4* qf = (const uint4*)g_qf16 +
            ((size_t)(h * 256 + qb * 4 + warp) * 4) * 32;
#pragma unroll
        for (int kk = 0; kk < 4; kk++)
            *(uint4*)qa[kk] = qf[kk * 32 + lane];
    }

    float m_s[2] = {-1e30f, -1e30f};
    float l_s[2] = {0.f, 0.f};
    float acc_o[8][4];
#pragma unroll
    for (int i = 0; i < 8; i++)
#pragma unroll
        for (int j = 0; j < 4; j++) acc_o[i][j] = 0.f;

    const int qrow0 = (warp << 4) + gq;

    const uint2* kf0 = (const uint2*)g_kf16 + ((size_t)kvh * 512 * 4) * 32;
    const uint2* vf0 = (const uint2*)g_vf16 + ((size_t)kvh * 256 * 8) * 32;

    uint2 buf[2][8];
#pragma unroll
    for (int nt = 0; nt < 8; nt++)
        buf[0][nt] = kf0[((nt << 2)) * 32 + lane];

    for (int kb = 0; kb <= qb; kb++) {
        const uint2* kf = kf0 + ((size_t)(kb * 8) * 4) * 32;
        const uint2* vf = vf0 + ((size_t)(kb * 4) * 8) * 32;

        float s[8][4];
#pragma unroll
        for (int nt = 0; nt < 8; nt++)
#pragma unroll
            for (int j = 0; j < 4; j++) s[nt][j] = 0.f;
#pragma unroll
        for (int kk = 0; kk < 4; kk++) {
            const int cur = kk & 1, nxt = cur ^ 1;
            if (kk < 3) {
#pragma unroll
                for (int nt = 0; nt < 8; nt++)
                    buf[nxt][nt] = kf[((nt << 2) | (kk + 1)) * 32 + lane];
            } else {
#pragma unroll
                for (int nt = 0; nt < 8; nt++)
                    buf[nxt][nt] = vf[nt * 32 + lane];
            }
#pragma unroll
            for (int nt = 0; nt < 8; nt++)
                mma_f16(s[nt], qa[kk], (const unsigned*)&buf[cur][nt]);
        }

        if (kb == qb) {
#pragma unroll
            for (int nt = 0; nt < 8; nt++) {
                int cb = (nt << 3) + (tq << 1);
                if (cb     > qrow0)     s[nt][0] = -1e30f;
                if (cb + 1 > qrow0)     s[nt][1] = -1e30f;
                if (cb     > qrow0 + 8) s[nt][2] = -1e30f;
                if (cb + 1 > qrow0 + 8) s[nt][3] = -1e30f;
            }
        }

        float mx0 = -1e30f, mx1 = -1e30f;
#pragma unroll
        for (int nt = 0; nt < 8; nt++) {
            mx0 = fmaxf(mx0, fmaxf(s[nt][0], s[nt][1]));
            mx1 = fmaxf(mx1, fmaxf(s[nt][2], s[nt][3]));
        }
        mx0 = fmaxf(mx0, __shfl_xor_sync(0xffffffffu, mx0, 1));
        mx0 = fmaxf(mx0, __shfl_xor_sync(0xffffffffu, mx0, 2));
        mx1 = fmaxf(mx1, __shfl_xor_sync(0xffffffffu, mx1, 1));
        mx1 = fmaxf(mx1, __shfl_xor_sync(0xffffffffu, mx1, 2));
        float nm0 = fmaxf(m_s[0], mx0), nm1 = fmaxf(m_s[1], mx1);
        float al0 = __expf(m_s[0] - nm0), al1 = __expf(m_s[1] - nm1);
        m_s[0] = nm0; m_s[1] = nm1;

        float sum0 = 0.f, sum1 = 0.f;
#pragma unroll
        for (int nt = 0; nt < 8; nt++) {
            s[nt][0] = __expf(s[nt][0] - nm0);
            s[nt][1] = __expf(s[nt][1] - nm0);
            s[nt][2] = __expf(s[nt][2] - nm1);
            s[nt][3] = __expf(s[nt][3] - nm1);
            sum0 += s[nt][0] + s[nt][1];
            sum1 += s[nt][2] + s[nt][3];
        }
        sum0 += __shfl_xor_sync(0xffffffffu, sum0, 1);
        sum0 += __shfl_xor_sync(0xffffffffu, sum0, 2);
        sum1 += __shfl_xor_sync(0xffffffffu, sum1, 1);
        sum1 += __shfl_xor_sync(0xffffffffu, sum1, 2);
        l_s[0] = l_s[0] * al0 + sum0;
        l_s[1] = l_s[1] * al1 + sum1;

#pragma unroll
        for (int nt = 0; nt < 8; nt++) {
            acc_o[nt][0] *= al0; acc_o[nt][1] *= al0;
            acc_o[nt][2] *= al1; acc_o[nt][3] *= al1;
        }

        const bool more = (kb < qb);
        const uint2* kf_next = kf + (8 * 4) * 32;
#pragma unroll
        for (int kk = 0; kk < 4; kk++) {
            const int cur = kk & 1, nxt = cur ^ 1;
            if (kk < 3) {
#pragma unroll
                for (int nt = 0; nt < 8; nt++)
                    buf[nxt][nt] = vf[(((kk + 1) << 3) | nt) * 32 + lane];
            } else if (more) {
#pragma unroll
                for (int nt = 0; nt < 8; nt++)
                    buf[nxt][nt] = kf_next[((nt << 2)) * 32 + lane];
            }
            unsigned pa[4];
            pa[0] = pack_h2(s[2 * kk][0],     s[2 * kk][1]);
            pa[1] = pack_h2(s[2 * kk][2],     s[2 * kk][3]);
            pa[2] = pack_h2(s[2 * kk + 1][0], s[2 * kk + 1][1]);
            pa[3] = pack_h2(s[2 * kk + 1][2], s[2 * kk + 1][3]);
#pragma unroll
            for (int nt = 0; nt < 8; nt++)
                mma_f16(acc_o[nt], pa, (const unsigned*)&buf[cur][nt]);
        }
    }

    // ---- epilogue: normalize + emit split-fp16 A-fragments of attn ----
    float inv0 = 1.0f / l_s[0];
    float inv1 = 1.0f / l_s[1];
    const int mt = qb * 4 + warp;
#pragma unroll
    for (int kk = 0; kk < 4; kk++) {
        float x0 = acc_o[2 * kk][0] * inv0,     x1 = acc_o[2 * kk][1] * inv0;
        float x2 = acc_o[2 * kk][2] * inv1,     x3 = acc_o[2 * kk][3] * inv1;
        float x4 = acc_o[2 * kk + 1][0] * inv0, x5 = acc_o[2 * kk + 1][1] * inv0;
        float x6 = acc_o[2 * kk + 1][2] * inv1, x7 = acc_o[2 * kk + 1][3] * inv1;
        uint4 hi, lo;
        split_h2(x0, x1, hi.x, lo.x);
        split_h2(x2, x3, hi.y, lo.y);
        split_h2(x4, x5, hi.z, lo.z);
        split_h2(x6, x7, hi.w, lo.w);
        size_t o = ((size_t)mt * 64 + (h * 4 + kk)) * 32 + lane;
        g_attn_h[o] = hi;
        g_attn_l[o] = lo;
    }
}

// ---------------------------------------------------------------------------
extern "C" void kernel_launch(void* const* d_in, const int* in_sizes, int n_in,
                              void* d_out, int out_size)
{
    const int*   positions = (const int*)d_in[0];
    const float* hidden    = (const float*)d_in[1];
    const float* w_qkv     = (const float*)d_in[2];
    const float* w_o       = (const float*)d_in[3];
    float*       out       = (float*)d_out;

    float* qkv = nullptr;
    cudaGetSymbolAddress((void**)&qkv, g_qkv);
    uint4 *hidh, *hidl, *attnh, *attnl;
    uint2 *wqh, *wql, *woh, *wol;
    cudaGetSymbolAddress((void**)&hidh, g_hid_h);
    cudaGetSymbolAddress((void**)&hidl, g_hid_l);
    cudaGetSymbolAddress((void**)&attnh, g_attn_h);
    cudaGetSymbolAddress((void**)&attnl, g_attn_l);
    cudaGetSymbolAddress((void**)&wqh, g_wqkv_h);
    cudaGetSymbolAddress((void**)&wql, g_wqkv_l);
    cudaGetSymbolAddress((void**)&woh, g_wo_h);
    cudaGetSymbolAddress((void**)&wol, g_wo_l);

    // 1) convert inputs to split-fp16 fragments (65536 warps)
    convert_in_kernel<<<65536 / 8, 256>>>(hidden, w_qkv, w_o);

    // 2) qkv = hidden @ w_qkv^T  (split-fp16 tensor GEMM)
    gemm_frag_kernel<<<dim3(QKV_N / 128, S_LEN / 128), 256>>>(
        hidh, hidl, wqh, wql, qkv, QKV_N, IN_DIM / 16);

    // 3) RoPE in place on q,k
    const int rope_total = S_LEN * (NH + NKV) * 32;
    rope_kernel<<<(rope_total + 255) / 256, 256>>>(positions);

    // 4) qkv -> flash fp16 fragments
    convert_frag_kernel<<<(7168 * 32) / 256, 256>>>();

    // 5) causal GQA flash attention; emits attn as split-fp16 A-frags
    flash_tc_kernel<<<dim3(S_LEN / 64, NH), 128>>>();

    // 6) out = attn @ w_o^T  (split-fp16 tensor GEMM)
    gemm_frag_kernel<<<dim3(HID / 128, S_LEN / 128), 256>>>(
        attnh, attnl, woh, wol, out, HID, QSIZE / 16);
}